// round 5
// baseline (speedup 1.0000x reference)
#include <cuda_runtime.h>
#include <math.h>

#define NMAX 16384

// 128 MB scratch for stacked, stored block-transposed:
// stackedT[tile][k][r], tile = n/64, r = n%64, k = v*128 + o
__device__ __align__(256) float g_stackedT[(size_t)NMAX * 2048];

static __device__ __forceinline__ float eluf(float t) { return t > 0.f ? t : expm1f(t); }
static __device__ __forceinline__ float sigm(float t) { return 1.f / (1.f + expf(-t)); }

// ---- packed f32x2 helpers (sm_100+) ----
static __device__ __forceinline__ unsigned long long pk2(float lo, float hi) {
    unsigned long long r;
    asm("mov.b64 %0, {%1, %2};" : "=l"(r) : "f"(lo), "f"(hi));
    return r;
}
static __device__ __forceinline__ void upk2(unsigned long long p, float& lo, float& hi) {
    asm("mov.b64 {%0, %1}, %2;" : "=f"(lo), "=f"(hi) : "l"(p));
}
static __device__ __forceinline__ void fma2(unsigned long long& d,
                                            unsigned long long a,
                                            unsigned long long b) {
    asm("fma.rn.f32x2 %0, %1, %2, %0;" : "+l"(d) : "l"(a), "l"(b));
}

// ---------------------------------------------------------------------------
// Stage 1: per-variable GRN + LayerNorm -> g_stackedT
// grid = (N/64, 16), 256 threads, 3 CTAs/SM (71.8 KB smem).
// Thread tile: 8 rows (rt = tid&7) x 1 output per 32-o chunk (ot = tid>>3).
// ---------------------------------------------------------------------------
__global__ void __launch_bounds__(256, 3) vsn_stage1(
    const float* __restrict__ x,
    const float* __restrict__ W1, const float* __restrict__ b1,
    const float* __restrict__ W2, const float* __restrict__ b2,
    const float* __restrict__ Wg, const float* __restrict__ bg,
    const float* __restrict__ Ws, const float* __restrict__ bs,
    const float* __restrict__ gamma, const float* __restrict__ beta)
{
    extern __shared__ float sm[];
    float* sh_h  = sm;            // [128][68]  h transposed: [d][r]
    float* sh_w2 = sm + 8704;     // [32][132]
    float* sh_wg = sm + 12928;    // [32][132]
    float* sh_ps = sm + 17152;    // [8][64] partial sums
    float* sh_q  = sm + 17664;    // [8][64] partial sumsq
    float* smean = sm + 18176;    // [64]
    float* srstd = sm + 18240;    // [64]
    float* sx    = sm + 18304;    // [64]
    // total 18368 floats = 73472 B

    const int tid = threadIdx.x;
    const int rt  = tid & 7;       // rows rt*8 .. rt*8+7
    const int ot  = tid >> 3;      // 0..31 ; o = oc + ot
    const int wrp = tid >> 5;
    const int v   = blockIdx.y;
    const int r0  = blockIdx.x * 64;

    for (int i = tid; i < 64; i += 256) sx[i] = x[(size_t)(r0 + i) * 16 + v];
    __syncthreads();

    // h[d][r] = elu(x[r]*W1[v,d] + b1[v,d])
    {
        const float* W1v = W1 + v * 128;
        const float* b1v = b1 + v * 128;
        for (int idx = tid; idx < 8192; idx += 256) {
            int r = idx & 63, d = idx >> 6;
            sh_h[d * 68 + r] = eluf(fmaf(sx[r], W1v[d], b1v[d]));
        }
    }

    float y[4][8];   // y[chunk][p]: o = chunk*32 + ot, row = rt*8+p

    for (int oc = 0; oc < 128; oc += 32) {
        __syncthreads();
        const float* W2b = W2 + ((size_t)v * 128 + oc) * 128;
        const float* Wgb = Wg + ((size_t)v * 128 + oc) * 128;
        for (int idx = tid; idx < 1024; idx += 256) {
            int o = idx >> 5, dq = (idx & 31) * 4;
            float4 a = *(const float4*)(W2b + o * 128 + dq);
            float* p = sh_w2 + o * 132 + dq;
            p[0] = a.x; p[1] = a.y; p[2] = a.z; p[3] = a.w;
            float4 b = *(const float4*)(Wgb + o * 128 + dq);
            float* q = sh_wg + o * 132 + dq;
            q[0] = b.x; q[1] = b.y; q[2] = b.z; q[3] = b.w;
        }
        __syncthreads();

        unsigned long long a2[4], ag[4];
        #pragma unroll
        for (int q = 0; q < 4; q++) { a2[q] = 0ull; ag[q] = 0ull; }

        const float* hrow = sh_h + rt * 8;
        const float* w2row = sh_w2 + ot * 132;
        const float* wgrow = sh_wg + ot * 132;
        #pragma unroll 4
        for (int d = 0; d < 128; d++) {
            ulonglong2 h01 = *(const ulonglong2*)(hrow + d * 68);
            ulonglong2 h23 = *(const ulonglong2*)(hrow + d * 68 + 4);
            float w2v = w2row[d];
            unsigned long long w2p = pk2(w2v, w2v);
            fma2(a2[0], h01.x, w2p);
            fma2(a2[1], h01.y, w2p);
            fma2(a2[2], h23.x, w2p);
            fma2(a2[3], h23.y, w2p);
            float wgv = wgrow[d];
            unsigned long long wgp = pk2(wgv, wgv);
            fma2(ag[0], h01.x, wgp);
            fma2(ag[1], h01.y, wgp);
            fma2(ag[2], h23.x, wgp);
            fma2(ag[3], h23.y, wgp);
        }

        // epilogue into registers
        {
            int o = oc + ot;
            int slot = oc >> 5;
            float b2v = b2[v * 128 + o];
            float bgv = bg[v * 128 + o];
            float wsv = Ws[v * 128 + o];
            float bsv = bs[v * 128 + o];
            #pragma unroll
            for (int q = 0; q < 4; q++) {
                float h2a, h2b, ga, gb;
                upk2(a2[q], h2a, h2b);
                upk2(ag[q], ga, gb);
                int p = q * 2;
                float g0 = sigm(ga + bgv);
                float g1 = sigm(gb + bgv);
                float sk0 = fmaf(sx[rt * 8 + p], wsv, bsv);
                float sk1 = fmaf(sx[rt * 8 + p + 1], wsv, bsv);
                y[slot][p]     = g0 * (h2a + b2v) + (1.f - g0) * sk0;
                y[slot][p + 1] = g1 * (h2b + b2v) + (1.f - g1) * sk1;
            }
        }
    }

    // LayerNorm partials: per-thread over its 4 o-values per row
    {
        float s[8], s2[8];
        #pragma unroll
        for (int p = 0; p < 8; p++) {
            float a = y[0][p] + y[1][p];
            float b = y[2][p] + y[3][p];
            s[p] = a + b;
            s2[p] = y[0][p] * y[0][p];
            s2[p] = fmaf(y[1][p], y[1][p], s2[p]);
            s2[p] = fmaf(y[2][p], y[2][p], s2[p]);
            s2[p] = fmaf(y[3][p], y[3][p], s2[p]);
        }
        #pragma unroll
        for (int p = 0; p < 8; p++) {
            s[p]  += __shfl_xor_sync(0xffffffffu, s[p], 8);
            s[p]  += __shfl_xor_sync(0xffffffffu, s[p], 16);
            s2[p] += __shfl_xor_sync(0xffffffffu, s2[p], 8);
            s2[p] += __shfl_xor_sync(0xffffffffu, s2[p], 16);
        }
        if ((ot & 3) == 0) {
            #pragma unroll
            for (int p = 0; p < 8; p++) {
                sh_ps[wrp * 64 + rt * 8 + p] = s[p];
                sh_q[wrp * 64 + rt * 8 + p] = s2[p];
            }
        }
    }
    __syncthreads();
    if (tid < 64) {
        float s = 0.f, s2 = 0.f;
        #pragma unroll
        for (int w = 0; w < 8; w++) { s += sh_ps[w * 64 + tid]; s2 += sh_q[w * 64 + tid]; }
        float m = s * 0.0078125f;
        float var = fmaf(-m, m, s2 * 0.0078125f);
        smean[tid] = m;
        srstd[tid] = rsqrtf(var + 1e-5f);
    }
    __syncthreads();

    // normalize in registers + write transposed to global
    {
        float mrow[8], rrow[8];
        #pragma unroll
        for (int p = 0; p < 8; p++) { mrow[p] = smean[rt * 8 + p]; rrow[p] = srstd[rt * 8 + p]; }
        float* dst = g_stackedT + ((size_t)blockIdx.x * 2048 + v * 128) * 64;
        const float* gv = gamma + v * 128;
        const float* bv = beta + v * 128;
        #pragma unroll
        for (int slot = 0; slot < 4; slot++) {
            int o = slot * 32 + ot;
            float go = gv[o], bo = bv[o];
            float4 oa, ob;
            oa.x = fmaf((y[slot][0] - mrow[0]) * rrow[0], go, bo);
            oa.y = fmaf((y[slot][1] - mrow[1]) * rrow[1], go, bo);
            oa.z = fmaf((y[slot][2] - mrow[2]) * rrow[2], go, bo);
            oa.w = fmaf((y[slot][3] - mrow[3]) * rrow[3], go, bo);
            ob.x = fmaf((y[slot][4] - mrow[4]) * rrow[4], go, bo);
            ob.y = fmaf((y[slot][5] - mrow[5]) * rrow[5], go, bo);
            ob.z = fmaf((y[slot][6] - mrow[6]) * rrow[6], go, bo);
            ob.w = fmaf((y[slot][7] - mrow[7]) * rrow[7], go, bo);
            *(float4*)(dst + o * 64 + rt * 8) = oa;
            *(float4*)(dst + o * 64 + rt * 8 + 4) = ob;
        }
    }
}

// ---------------------------------------------------------------------------
// Stage 2: softmax GRN + weighted sum. grid = N/64, 256 threads, 2 CTAs/SM.
// Thread tile: 8 rows (rt = tid&7) x 4 hs-outputs (jt = tid>>3, j = jt*4+i).
// K chunked by 64 (32 chunks) to shrink smem to 84.5 KB.
// ---------------------------------------------------------------------------
__global__ void __launch_bounds__(256, 2) vsn_stage2(
    const float* __restrict__ sW1, const float* __restrict__ sb1,
    const float* __restrict__ sW2, const float* __restrict__ sb2,
    const float* __restrict__ sWg, const float* __restrict__ sbg,
    const float* __restrict__ sWs, const float* __restrict__ sbs,
    const float* __restrict__ sgamma, const float* __restrict__ sbeta,
    float* __restrict__ outp, float* __restrict__ outw)
{
    extern __shared__ float sm[];
    float* sh_f  = sm;            // [64 k][64 r] flat chunk
    float* warea = sm + 4096;     // 12672 floats, multi-use
    float* sh_ws = sm + 16768;    // [16][68]
    float* sh_sk = sm + 17856;    // [64][17]
    float* sh_z  = sm + 18944;    // [64][17]
    float* sh_w  = sm + 20032;    // [64][17]
    // total 21120 floats = 84480 B

    float* sh_w1 = warea;           // [128][68] during main GEMM
    float* sh_hs = warea;           // [64][133]  after GEMM
    float* sh_s2 = warea + 8512;    // [16][130]
    float* sh_sg = warea + 10592;   // [16][130]
    float* sh_p3 = warea;           // [128][64]  pass-3 data
    float* sh_o  = warea;           // [64][132]  pass-3 output staging

    const int tid = threadIdx.x;
    const int rt = tid & 7;         // rows rt*8 .. rt*8+7
    const int jt = tid >> 3;        // 0..31 ; j = jt*4+i
    const int v16 = jt & 15;
    const int tile = blockIdx.x;
    const size_t rowbase = (size_t)tile * 64;
    const float* fbase = g_stackedT + (size_t)tile * 2048 * 64;

    unsigned long long acc[4][4];   // [i][rowpair]
    unsigned long long accs[4];
    #pragma unroll
    for (int i = 0; i < 4; i++) {
        accs[i] = 0ull;
        #pragma unroll
        for (int q = 0; q < 4; q++) acc[i][q] = 0ull;
    }

    // ---- main GEMM: hs (64x128) and sks (64x16) over K=2048 in 32 chunks ----
    for (int c = 0; c < 32; c++) {
        __syncthreads();
        {
            const float4* src = (const float4*)(fbase + (size_t)c * 64 * 64);
            float4* dst = (float4*)sh_f;
            for (int idx = tid; idx < 1024; idx += 256) dst[idx] = src[idx];
        }
        for (int idx = tid; idx < 2048; idx += 256) {
            int j = idx >> 4, kq = (idx & 15) * 4;
            float4 a = *(const float4*)(sW1 + (size_t)j * 2048 + c * 64 + kq);
            float* p = sh_w1 + j * 68 + kq;
            p[0] = a.x; p[1] = a.y; p[2] = a.z; p[3] = a.w;
        }
        for (int idx = tid; idx < 256; idx += 256) {
            int vv = idx >> 4, kq = (idx & 15) * 4;
            float4 a = *(const float4*)(sWs + (size_t)vv * 2048 + c * 64 + kq);
            float* p = sh_ws + vv * 68 + kq;
            p[0] = a.x; p[1] = a.y; p[2] = a.z; p[3] = a.w;
        }
        __syncthreads();

        const float* frow = sh_f + rt * 8;
        const float* wsrow = sh_ws + v16 * 68;
        #pragma unroll 4
        for (int kk = 0; kk < 64; kk++) {
            ulonglong2 f01 = *(const ulonglong2*)(frow + kk * 64);
            ulonglong2 f23 = *(const ulonglong2*)(frow + kk * 64 + 4);
            float wsv = wsrow[kk];
            unsigned long long wsp = pk2(wsv, wsv);
            fma2(accs[0], f01.x, wsp);
            fma2(accs[1], f01.y, wsp);
            fma2(accs[2], f23.x, wsp);
            fma2(accs[3], f23.y, wsp);
            #pragma unroll
            for (int i = 0; i < 4; i++) {
                float w = sh_w1[(jt * 4 + i) * 68 + kk];
                unsigned long long wp = pk2(w, w);
                fma2(acc[i][0], f01.x, wp);
                fma2(acc[i][1], f01.y, wp);
                fma2(acc[i][2], f23.x, wp);
                fma2(acc[i][3], f23.y, wp);
            }
        }
    }
    __syncthreads();   // sh_w1 reads done; safe to overlay

    // sks -> shared (only jt<16), hs (elu) -> shared
    if (jt < 16) {
        float sbsv = sbs[v16];
        #pragma unroll
        for (int q = 0; q < 4; q++) {
            float a, b;
            upk2(accs[q], a, b);
            sh_sk[(rt * 8 + q * 2) * 17 + v16] = a + sbsv;
            sh_sk[(rt * 8 + q * 2 + 1) * 17 + v16] = b + sbsv;
        }
    }
    #pragma unroll
    for (int i = 0; i < 4; i++) {
        int jj = jt * 4 + i;
        float bb = sb1[jj];
        #pragma unroll
        for (int q = 0; q < 4; q++) {
            float a, b;
            upk2(acc[i][q], a, b);
            sh_hs[(rt * 8 + q * 2) * 133 + jj] = eluf(a + bb);
            sh_hs[(rt * 8 + q * 2 + 1) * 133 + jj] = eluf(b + bb);
        }
    }
    for (int idx = tid; idx < 512; idx += 256) {
        int vv = idx >> 5, jq = (idx & 31) * 4;
        float4 a = *(const float4*)(sW2 + vv * 128 + jq);
        float* p = sh_s2 + vv * 130 + jq;
        p[0] = a.x; p[1] = a.y; p[2] = a.z; p[3] = a.w;
        float4 b = *(const float4*)(sWg + vv * 128 + jq);
        float* q = sh_sg + vv * 130 + jq;
        q[0] = b.x; q[1] = b.y; q[2] = b.z; q[3] = b.w;
    }
    __syncthreads();

    // tiny GEMM 128 -> 16 (x2) and GRN combine: thread = (row, quarter of v's)
    {
        int q = tid & 3, r = tid >> 2;
        float a2[4] = {0.f, 0.f, 0.f, 0.f};
        float ag[4] = {0.f, 0.f, 0.f, 0.f};
        #pragma unroll 4
        for (int j = 0; j < 128; j++) {
            float hsv = sh_hs[r * 133 + j];
            #pragma unroll
            for (int i = 0; i < 4; i++) {
                a2[i] = fmaf(hsv, sh_s2[(q * 4 + i) * 130 + j], a2[i]);
                ag[i] = fmaf(hsv, sh_sg[(q * 4 + i) * 130 + j], ag[i]);
            }
        }
        #pragma unroll
        for (int i = 0; i < 4; i++) {
            int vv = q * 4 + i;
            float h2s = a2[i] + sb2[vv];
            float gs = sigm(ag[i] + sbg[vv]);
            float sk = sh_sk[r * 17 + vv];
            sh_z[r * 17 + vv] = gs * h2s + (1.f - gs) * sk;
        }
    }
    __syncthreads();

    // LN over 16 + softmax, one thread per row
    if (tid < 64) {
        float zz[16];
        float s = 0.f;
        #pragma unroll
        for (int vv = 0; vv < 16; vv++) { zz[vv] = sh_z[tid * 17 + vv]; s += zz[vv]; }
        float m = s * 0.0625f;
        float s2 = 0.f;
        #pragma unroll
        for (int vv = 0; vv < 16; vv++) { float d = zz[vv] - m; s2 = fmaf(d, d, s2); }
        float rstd = rsqrtf(s2 * 0.0625f + 1e-5f);
        float mx = -3.4e38f;
        #pragma unroll
        for (int vv = 0; vv < 16; vv++) {
            zz[vv] = fmaf((zz[vv] - m) * rstd, sgamma[vv], sbeta[vv]);
            mx = fmaxf(mx, zz[vv]);
        }
        float se = 0.f;
        #pragma unroll
        for (int vv = 0; vv < 16; vv++) { zz[vv] = expf(zz[vv] - mx); se += zz[vv]; }
        float inv = 1.f / se;
        #pragma unroll
        for (int vv = 0; vv < 16; vv++) sh_w[tid * 17 + vv] = zz[vv] * inv;
    }
    __syncthreads();

    // weights out (coalesced)
    for (int idx = tid; idx < 1024; idx += 256) {
        int r = idx >> 4, vv = idx & 15;
        outw[(rowbase + r) * 16 + vv] = sh_w[r * 17 + vv];
    }

    // ---- pass 3: processed[r][d] = sum_v stacked[r][v][d] * w[r][v] ----
    unsigned long long accp[4][4];
    #pragma unroll
    for (int i = 0; i < 4; i++)
        #pragma unroll
        for (int q = 0; q < 4; q++) accp[i][q] = 0ull;

    for (int vv = 0; vv < 16; vv++) {
        __syncthreads();
        {
            const float4* src = (const float4*)(fbase + (size_t)vv * 128 * 64);
            float4* dst = (float4*)sh_p3;
            for (int idx = tid; idx < 2048; idx += 256) dst[idx] = src[idx];
        }
        __syncthreads();
        unsigned long long wp[4];
        #pragma unroll
        for (int q = 0; q < 4; q++)
            wp[q] = pk2(sh_w[(rt * 8 + q * 2) * 17 + vv],
                        sh_w[(rt * 8 + q * 2 + 1) * 17 + vv]);
        #pragma unroll
        for (int i = 0; i < 4; i++) {
            const float* fp = sh_p3 + (jt * 4 + i) * 64 + rt * 8;
            ulonglong2 f01 = *(const ulonglong2*)fp;
            ulonglong2 f23 = *(const ulonglong2*)(fp + 4);
            fma2(accp[i][0], f01.x, wp[0]);
            fma2(accp[i][1], f01.y, wp[1]);
            fma2(accp[i][2], f23.x, wp[2]);
            fma2(accp[i][3], f23.y, wp[3]);
        }
    }
    __syncthreads();
    #pragma unroll
    for (int i = 0; i < 4; i++) {
        int d = jt * 4 + i;
        #pragma unroll
        for (int q = 0; q < 4; q++) {
            float a, b;
            upk2(accp[i][q], a, b);
            sh_o[(rt * 8 + q * 2) * 132 + d] = a;
            sh_o[(rt * 8 + q * 2 + 1) * 132 + d] = b;
        }
    }
    __syncthreads();
    for (int idx = tid; idx < 2048; idx += 256) {
        int r = idx >> 5, dq = (idx & 31) * 4;
        float4 a = *(const float4*)(sh_o + r * 132 + dq);
        *(float4*)(outp + (rowbase + r) * 128 + dq) = a;
    }
}

// ---------------------------------------------------------------------------
extern "C" void kernel_launch(void* const* d_in, const int* in_sizes, int n_in,
                              void* d_out, int out_size) {
    const float* x      = (const float*)d_in[0];
    const float* W1     = (const float*)d_in[1];
    const float* b1     = (const float*)d_in[2];
    const float* W2     = (const float*)d_in[3];
    const float* b2     = (const float*)d_in[4];
    const float* Wg     = (const float*)d_in[5];
    const float* bg     = (const float*)d_in[6];
    const float* Ws     = (const float*)d_in[7];
    const float* bs     = (const float*)d_in[8];
    const float* gamma  = (const float*)d_in[9];
    const float* beta   = (const float*)d_in[10];
    const float* sW1    = (const float*)d_in[11];
    const float* sb1    = (const float*)d_in[12];
    const float* sW2    = (const float*)d_in[13];
    const float* sb2    = (const float*)d_in[14];
    const float* sWg    = (const float*)d_in[15];
    const float* sbg    = (const float*)d_in[16];
    const float* sWs    = (const float*)d_in[17];
    const float* sbs    = (const float*)d_in[18];
    const float* sgamma = (const float*)d_in[19];
    const float* sbeta  = (const float*)d_in[20];

    int N = in_sizes[0] / 16;          // 16384 rows
    int tiles = N / 64;                // 256

    float* outp = (float*)d_out;
    float* outw = outp + (size_t)N * 128;

    cudaFuncSetAttribute(vsn_stage1, cudaFuncAttributeMaxDynamicSharedMemorySize, 73472);
    cudaFuncSetAttribute(vsn_stage2, cudaFuncAttributeMaxDynamicSharedMemorySize, 84480);

    dim3 g1(tiles, 16);
    vsn_stage1<<<g1, 256, 73472>>>(x, W1, b1, W2, b2, Wg, bg, Ws, bs, gamma, beta);
    vsn_stage2<<<tiles, 256, 84480>>>(sW1, sb1, sW2, sb2, sWg, sbg, sWs, sbs,
                                      sgamma, sbeta, outp, outw);
}

// round 6
// speedup vs baseline: 1.0002x; 1.0002x over previous
#include <cuda_runtime.h>
#include <math.h>

#define NMAX 16384

// 128 MB scratch for stacked, stored block-transposed:
// stackedT[tile][k][r], tile = n/64, r = n%64, k = v*128 + o
__device__ __align__(256) float g_stackedT[(size_t)NMAX * 2048];

static __device__ __forceinline__ float eluf(float t) { return t > 0.f ? t : expm1f(t); }
static __device__ __forceinline__ float sigm(float t) { return 1.f / (1.f + expf(-t)); }

// ---- packed f32x2 helpers (sm_100+) ----
static __device__ __forceinline__ unsigned long long pk2(float lo, float hi) {
    unsigned long long r;
    asm("mov.b64 %0, {%1, %2};" : "=l"(r) : "f"(lo), "f"(hi));
    return r;
}
static __device__ __forceinline__ void upk2(unsigned long long p, float& lo, float& hi) {
    asm("mov.b64 {%0, %1}, %2;" : "=f"(lo), "=f"(hi) : "l"(p));
}
static __device__ __forceinline__ void fma2(unsigned long long& d,
                                            unsigned long long a,
                                            unsigned long long b) {
    asm("fma.rn.f32x2 %0, %1, %2, %0;" : "+l"(d) : "l"(a), "l"(b));
}

// ---------------------------------------------------------------------------
// Stage 1: per-variable GRN + LayerNorm -> g_stackedT
// grid = (N/64, 16), 256 threads, 3 CTAs/SM (71.8 KB smem).
// Thread tile: 8 rows (rt = tid&7) x 1 output per 32-o chunk (ot = tid>>3).
// ---------------------------------------------------------------------------
__global__ void __launch_bounds__(256, 3) vsn_stage1(
    const float* __restrict__ x,
    const float* __restrict__ W1, const float* __restrict__ b1,
    const float* __restrict__ W2, const float* __restrict__ b2,
    const float* __restrict__ Wg, const float* __restrict__ bg,
    const float* __restrict__ Ws, const float* __restrict__ bs,
    const float* __restrict__ gamma, const float* __restrict__ beta)
{
    extern __shared__ float sm[];
    float* sh_h  = sm;            // [128][68]  h transposed: [d][r]
    float* sh_w2 = sm + 8704;     // [32][132]
    float* sh_wg = sm + 12928;    // [32][132]
    float* sh_ps = sm + 17152;    // [8][64] partial sums
    float* sh_q  = sm + 17664;    // [8][64] partial sumsq
    float* smean = sm + 18176;    // [64]
    float* srstd = sm + 18240;    // [64]
    float* sx    = sm + 18304;    // [64]
    // total 18368 floats = 73472 B

    const int tid = threadIdx.x;
    const int rt  = tid & 7;       // rows rt*8 .. rt*8+7
    const int ot  = tid >> 3;      // 0..31 ; o = oc + ot
    const int wrp = tid >> 5;
    const int v   = blockIdx.y;
    const int r0  = blockIdx.x * 64;

    for (int i = tid; i < 64; i += 256) sx[i] = x[(size_t)(r0 + i) * 16 + v];
    __syncthreads();

    // h[d][r] = elu(x[r]*W1[v,d] + b1[v,d])
    {
        const float* W1v = W1 + v * 128;
        const float* b1v = b1 + v * 128;
        for (int idx = tid; idx < 8192; idx += 256) {
            int r = idx & 63, d = idx >> 6;
            sh_h[d * 68 + r] = eluf(fmaf(sx[r], W1v[d], b1v[d]));
        }
    }

    float y[4][8];   // y[chunk][p]: o = chunk*32 + ot, row = rt*8+p

    for (int oc = 0; oc < 128; oc += 32) {
        __syncthreads();
        const float* W2b = W2 + ((size_t)v * 128 + oc) * 128;
        const float* Wgb = Wg + ((size_t)v * 128 + oc) * 128;
        for (int idx = tid; idx < 1024; idx += 256) {
            int o = idx >> 5, dq = (idx & 31) * 4;
            float4 a = *(const float4*)(W2b + o * 128 + dq);
            float* p = sh_w2 + o * 132 + dq;
            p[0] = a.x; p[1] = a.y; p[2] = a.z; p[3] = a.w;
            float4 b = *(const float4*)(Wgb + o * 128 + dq);
            float* q = sh_wg + o * 132 + dq;
            q[0] = b.x; q[1] = b.y; q[2] = b.z; q[3] = b.w;
        }
        __syncthreads();

        unsigned long long a2[4], ag[4];
        #pragma unroll
        for (int q = 0; q < 4; q++) { a2[q] = 0ull; ag[q] = 0ull; }

        const float* hrow = sh_h + rt * 8;
        const float* w2row = sh_w2 + ot * 132;
        const float* wgrow = sh_wg + ot * 132;
        #pragma unroll 4
        for (int d = 0; d < 128; d++) {
            ulonglong2 h01 = *(const ulonglong2*)(hrow + d * 68);
            ulonglong2 h23 = *(const ulonglong2*)(hrow + d * 68 + 4);
            float w2v = w2row[d];
            unsigned long long w2p = pk2(w2v, w2v);
            fma2(a2[0], h01.x, w2p);
            fma2(a2[1], h01.y, w2p);
            fma2(a2[2], h23.x, w2p);
            fma2(a2[3], h23.y, w2p);
            float wgv = wgrow[d];
            unsigned long long wgp = pk2(wgv, wgv);
            fma2(ag[0], h01.x, wgp);
            fma2(ag[1], h01.y, wgp);
            fma2(ag[2], h23.x, wgp);
            fma2(ag[3], h23.y, wgp);
        }

        // epilogue into registers
        {
            int o = oc + ot;
            int slot = oc >> 5;
            float b2v = b2[v * 128 + o];
            float bgv = bg[v * 128 + o];
            float wsv = Ws[v * 128 + o];
            float bsv = bs[v * 128 + o];
            #pragma unroll
            for (int q = 0; q < 4; q++) {
                float h2a, h2b, ga, gb;
                upk2(a2[q], h2a, h2b);
                upk2(ag[q], ga, gb);
                int p = q * 2;
                float g0 = sigm(ga + bgv);
                float g1 = sigm(gb + bgv);
                float sk0 = fmaf(sx[rt * 8 + p], wsv, bsv);
                float sk1 = fmaf(sx[rt * 8 + p + 1], wsv, bsv);
                y[slot][p]     = g0 * (h2a + b2v) + (1.f - g0) * sk0;
                y[slot][p + 1] = g1 * (h2b + b2v) + (1.f - g1) * sk1;
            }
        }
    }

    // LayerNorm partials: per-thread over its 4 o-values per row
    {
        float s[8], s2[8];
        #pragma unroll
        for (int p = 0; p < 8; p++) {
            float a = y[0][p] + y[1][p];
            float b = y[2][p] + y[3][p];
            s[p] = a + b;
            s2[p] = y[0][p] * y[0][p];
            s2[p] = fmaf(y[1][p], y[1][p], s2[p]);
            s2[p] = fmaf(y[2][p], y[2][p], s2[p]);
            s2[p] = fmaf(y[3][p], y[3][p], s2[p]);
        }
        #pragma unroll
        for (int p = 0; p < 8; p++) {
            s[p]  += __shfl_xor_sync(0xffffffffu, s[p], 8);
            s[p]  += __shfl_xor_sync(0xffffffffu, s[p], 16);
            s2[p] += __shfl_xor_sync(0xffffffffu, s2[p], 8);
            s2[p] += __shfl_xor_sync(0xffffffffu, s2[p], 16);
        }
        if ((ot & 3) == 0) {
            #pragma unroll
            for (int p = 0; p < 8; p++) {
                sh_ps[wrp * 64 + rt * 8 + p] = s[p];
                sh_q[wrp * 64 + rt * 8 + p] = s2[p];
            }
        }
    }
    __syncthreads();
    if (tid < 64) {
        float s = 0.f, s2 = 0.f;
        #pragma unroll
        for (int w = 0; w < 8; w++) { s += sh_ps[w * 64 + tid]; s2 += sh_q[w * 64 + tid]; }
        float m = s * 0.0078125f;
        float var = fmaf(-m, m, s2 * 0.0078125f);
        smean[tid] = m;
        srstd[tid] = rsqrtf(var + 1e-5f);
    }
    __syncthreads();

    // normalize in registers + write transposed to global
    {
        float mrow[8], rrow[8];
        #pragma unroll
        for (int p = 0; p < 8; p++) { mrow[p] = smean[rt * 8 + p]; rrow[p] = srstd[rt * 8 + p]; }
        float* dst = g_stackedT + ((size_t)blockIdx.x * 2048 + v * 128) * 64;
        const float* gv = gamma + v * 128;
        const float* bv = beta + v * 128;
        #pragma unroll
        for (int slot = 0; slot < 4; slot++) {
            int o = slot * 32 + ot;
            float go = gv[o], bo = bv[o];
            float4 oa, ob;
            oa.x = fmaf((y[slot][0] - mrow[0]) * rrow[0], go, bo);
            oa.y = fmaf((y[slot][1] - mrow[1]) * rrow[1], go, bo);
            oa.z = fmaf((y[slot][2] - mrow[2]) * rrow[2], go, bo);
            oa.w = fmaf((y[slot][3] - mrow[3]) * rrow[3], go, bo);
            ob.x = fmaf((y[slot][4] - mrow[4]) * rrow[4], go, bo);
            ob.y = fmaf((y[slot][5] - mrow[5]) * rrow[5], go, bo);
            ob.z = fmaf((y[slot][6] - mrow[6]) * rrow[6], go, bo);
            ob.w = fmaf((y[slot][7] - mrow[7]) * rrow[7], go, bo);
            *(float4*)(dst + o * 64 + rt * 8) = oa;
            *(float4*)(dst + o * 64 + rt * 8 + 4) = ob;
        }
    }
}

// ---------------------------------------------------------------------------
// Stage 2: softmax GRN + weighted sum. grid = N/64, 256 threads, 2 CTAs/SM.
// Thread tile: 8 rows (rt = tid&7) x 4 hs-outputs (jt = tid>>3, j = jt*4+i).
// K chunked by 64 (32 chunks) to shrink smem to 84.5 KB.
// ---------------------------------------------------------------------------
__global__ void __launch_bounds__(256, 2) vsn_stage2(
    const float* __restrict__ sW1, const float* __restrict__ sb1,
    const float* __restrict__ sW2, const float* __restrict__ sb2,
    const float* __restrict__ sWg, const float* __restrict__ sbg,
    const float* __restrict__ sWs, const float* __restrict__ sbs,
    const float* __restrict__ sgamma, const float* __restrict__ sbeta,
    float* __restrict__ outp, float* __restrict__ outw)
{
    extern __shared__ float sm[];
    float* sh_f  = sm;            // [64 k][64 r] flat chunk
    float* warea = sm + 4096;     // 12672 floats, multi-use
    float* sh_ws = sm + 16768;    // [16][68]
    float* sh_sk = sm + 17856;    // [64][17]
    float* sh_z  = sm + 18944;    // [64][17]
    float* sh_w  = sm + 20032;    // [64][17]
    // total 21120 floats = 84480 B

    float* sh_w1 = warea;           // [128][68] during main GEMM
    float* sh_hs = warea;           // [64][133]  after GEMM
    float* sh_s2 = warea + 8512;    // [16][130]
    float* sh_sg = warea + 10592;   // [16][130]
    float* sh_p3 = warea;           // [128][64]  pass-3 data
    float* sh_o  = warea;           // [64][132]  pass-3 output staging

    const int tid = threadIdx.x;
    const int rt = tid & 7;         // rows rt*8 .. rt*8+7
    const int jt = tid >> 3;        // 0..31 ; j = jt*4+i
    const int v16 = jt & 15;
    const int tile = blockIdx.x;
    const size_t rowbase = (size_t)tile * 64;
    const float* fbase = g_stackedT + (size_t)tile * 2048 * 64;

    unsigned long long acc[4][4];   // [i][rowpair]
    unsigned long long accs[4];
    #pragma unroll
    for (int i = 0; i < 4; i++) {
        accs[i] = 0ull;
        #pragma unroll
        for (int q = 0; q < 4; q++) acc[i][q] = 0ull;
    }

    // ---- main GEMM: hs (64x128) and sks (64x16) over K=2048 in 32 chunks ----
    for (int c = 0; c < 32; c++) {
        __syncthreads();
        {
            const float4* src = (const float4*)(fbase + (size_t)c * 64 * 64);
            float4* dst = (float4*)sh_f;
            for (int idx = tid; idx < 1024; idx += 256) dst[idx] = src[idx];
        }
        for (int idx = tid; idx < 2048; idx += 256) {
            int j = idx >> 4, kq = (idx & 15) * 4;
            float4 a = *(const float4*)(sW1 + (size_t)j * 2048 + c * 64 + kq);
            float* p = sh_w1 + j * 68 + kq;
            p[0] = a.x; p[1] = a.y; p[2] = a.z; p[3] = a.w;
        }
        for (int idx = tid; idx < 256; idx += 256) {
            int vv = idx >> 4, kq = (idx & 15) * 4;
            float4 a = *(const float4*)(sWs + (size_t)vv * 2048 + c * 64 + kq);
            float* p = sh_ws + vv * 68 + kq;
            p[0] = a.x; p[1] = a.y; p[2] = a.z; p[3] = a.w;
        }
        __syncthreads();

        const float* frow = sh_f + rt * 8;
        const float* wsrow = sh_ws + v16 * 68;
        #pragma unroll 4
        for (int kk = 0; kk < 64; kk++) {
            ulonglong2 f01 = *(const ulonglong2*)(frow + kk * 64);
            ulonglong2 f23 = *(const ulonglong2*)(frow + kk * 64 + 4);
            float wsv = wsrow[kk];
            unsigned long long wsp = pk2(wsv, wsv);
            fma2(accs[0], f01.x, wsp);
            fma2(accs[1], f01.y, wsp);
            fma2(accs[2], f23.x, wsp);
            fma2(accs[3], f23.y, wsp);
            #pragma unroll
            for (int i = 0; i < 4; i++) {
                float w = sh_w1[(jt * 4 + i) * 68 + kk];
                unsigned long long wp = pk2(w, w);
                fma2(acc[i][0], f01.x, wp);
                fma2(acc[i][1], f01.y, wp);
                fma2(acc[i][2], f23.x, wp);
                fma2(acc[i][3], f23.y, wp);
            }
        }
    }
    __syncthreads();   // sh_w1 reads done; safe to overlay

    // sks -> shared (only jt<16), hs (elu) -> shared
    if (jt < 16) {
        float sbsv = sbs[v16];
        #pragma unroll
        for (int q = 0; q < 4; q++) {
            float a, b;
            upk2(accs[q], a, b);
            sh_sk[(rt * 8 + q * 2) * 17 + v16] = a + sbsv;
            sh_sk[(rt * 8 + q * 2 + 1) * 17 + v16] = b + sbsv;
        }
    }
    #pragma unroll
    for (int i = 0; i < 4; i++) {
        int jj = jt * 4 + i;
        float bb = sb1[jj];
        #pragma unroll
        for (int q = 0; q < 4; q++) {
            float a, b;
            upk2(acc[i][q], a, b);
            sh_hs[(rt * 8 + q * 2) * 133 + jj] = eluf(a + bb);
            sh_hs[(rt * 8 + q * 2 + 1) * 133 + jj] = eluf(b + bb);
        }
    }
    for (int idx = tid; idx < 512; idx += 256) {
        int vv = idx >> 5, jq = (idx & 31) * 4;
        float4 a = *(const float4*)(sW2 + vv * 128 + jq);
        float* p = sh_s2 + vv * 130 + jq;
        p[0] = a.x; p[1] = a.y; p[2] = a.z; p[3] = a.w;
        float4 b = *(const float4*)(sWg + vv * 128 + jq);
        float* q = sh_sg + vv * 130 + jq;
        q[0] = b.x; q[1] = b.y; q[2] = b.z; q[3] = b.w;
    }
    __syncthreads();

    // tiny GEMM 128 -> 16 (x2) and GRN combine: thread = (row, quarter of v's)
    {
        int q = tid & 3, r = tid >> 2;
        float a2[4] = {0.f, 0.f, 0.f, 0.f};
        float ag[4] = {0.f, 0.f, 0.f, 0.f};
        #pragma unroll 4
        for (int j = 0; j < 128; j++) {
            float hsv = sh_hs[r * 133 + j];
            #pragma unroll
            for (int i = 0; i < 4; i++) {
                a2[i] = fmaf(hsv, sh_s2[(q * 4 + i) * 130 + j], a2[i]);
                ag[i] = fmaf(hsv, sh_sg[(q * 4 + i) * 130 + j], ag[i]);
            }
        }
        #pragma unroll
        for (int i = 0; i < 4; i++) {
            int vv = q * 4 + i;
            float h2s = a2[i] + sb2[vv];
            float gs = sigm(ag[i] + sbg[vv]);
            float sk = sh_sk[r * 17 + vv];
            sh_z[r * 17 + vv] = gs * h2s + (1.f - gs) * sk;
        }
    }
    __syncthreads();

    // LN over 16 + softmax, one thread per row
    if (tid < 64) {
        float zz[16];
        float s = 0.f;
        #pragma unroll
        for (int vv = 0; vv < 16; vv++) { zz[vv] = sh_z[tid * 17 + vv]; s += zz[vv]; }
        float m = s * 0.0625f;
        float s2 = 0.f;
        #pragma unroll
        for (int vv = 0; vv < 16; vv++) { float d = zz[vv] - m; s2 = fmaf(d, d, s2); }
        float rstd = rsqrtf(s2 * 0.0625f + 1e-5f);
        float mx = -3.4e38f;
        #pragma unroll
        for (int vv = 0; vv < 16; vv++) {
            zz[vv] = fmaf((zz[vv] - m) * rstd, sgamma[vv], sbeta[vv]);
            mx = fmaxf(mx, zz[vv]);
        }
        float se = 0.f;
        #pragma unroll
        for (int vv = 0; vv < 16; vv++) { zz[vv] = expf(zz[vv] - mx); se += zz[vv]; }
        float inv = 1.f / se;
        #pragma unroll
        for (int vv = 0; vv < 16; vv++) sh_w[tid * 17 + vv] = zz[vv] * inv;
    }
    __syncthreads();

    // weights out (coalesced)
    for (int idx = tid; idx < 1024; idx += 256) {
        int r = idx >> 4, vv = idx & 15;
        outw[(rowbase + r) * 16 + vv] = sh_w[r * 17 + vv];
    }

    // ---- pass 3: processed[r][d] = sum_v stacked[r][v][d] * w[r][v] ----
    unsigned long long accp[4][4];
    #pragma unroll
    for (int i = 0; i < 4; i++)
        #pragma unroll
        for (int q = 0; q < 4; q++) accp[i][q] = 0ull;

    for (int vv = 0; vv < 16; vv++) {
        __syncthreads();
        {
            const float4* src = (const float4*)(fbase + (size_t)vv * 128 * 64);
            float4* dst = (float4*)sh_p3;
            for (int idx = tid; idx < 2048; idx += 256) dst[idx] = src[idx];
        }
        __syncthreads();
        unsigned long long wp[4];
        #pragma unroll
        for (int q = 0; q < 4; q++)
            wp[q] = pk2(sh_w[(rt * 8 + q * 2) * 17 + vv],
                        sh_w[(rt * 8 + q * 2 + 1) * 17 + vv]);
        #pragma unroll
        for (int i = 0; i < 4; i++) {
            const float* fp = sh_p3 + (jt * 4 + i) * 64 + rt * 8;
            ulonglong2 f01 = *(const ulonglong2*)fp;
            ulonglong2 f23 = *(const ulonglong2*)(fp + 4);
            fma2(accp[i][0], f01.x, wp[0]);
            fma2(accp[i][1], f01.y, wp[1]);
            fma2(accp[i][2], f23.x, wp[2]);
            fma2(accp[i][3], f23.y, wp[3]);
        }
    }
    __syncthreads();
    #pragma unroll
    for (int i = 0; i < 4; i++) {
        int d = jt * 4 + i;
        #pragma unroll
        for (int q = 0; q < 4; q++) {
            float a, b;
            upk2(accp[i][q], a, b);
            sh_o[(rt * 8 + q * 2) * 132 + d] = a;
            sh_o[(rt * 8 + q * 2 + 1) * 132 + d] = b;
        }
    }
    __syncthreads();
    for (int idx = tid; idx < 2048; idx += 256) {
        int r = idx >> 5, dq = (idx & 31) * 4;
        float4 a = *(const float4*)(sh_o + r * 132 + dq);
        *(float4*)(outp + (rowbase + r) * 128 + dq) = a;
    }
}

// ---------------------------------------------------------------------------
extern "C" void kernel_launch(void* const* d_in, const int* in_sizes, int n_in,
                              void* d_out, int out_size) {
    const float* x      = (const float*)d_in[0];
    const float* W1     = (const float*)d_in[1];
    const float* b1     = (const float*)d_in[2];
    const float* W2     = (const float*)d_in[3];
    const float* b2     = (const float*)d_in[4];
    const float* Wg     = (const float*)d_in[5];
    const float* bg     = (const float*)d_in[6];
    const float* Ws     = (const float*)d_in[7];
    const float* bs     = (const float*)d_in[8];
    const float* gamma  = (const float*)d_in[9];
    const float* beta   = (const float*)d_in[10];
    const float* sW1    = (const float*)d_in[11];
    const float* sb1    = (const float*)d_in[12];
    const float* sW2    = (const float*)d_in[13];
    const float* sb2    = (const float*)d_in[14];
    const float* sWg    = (const float*)d_in[15];
    const float* sbg    = (const float*)d_in[16];
    const float* sWs    = (const float*)d_in[17];
    const float* sbs    = (const float*)d_in[18];
    const float* sgamma = (const float*)d_in[19];
    const float* sbeta  = (const float*)d_in[20];

    int N = in_sizes[0] / 16;          // 16384 rows
    int tiles = N / 64;                // 256

    float* outp = (float*)d_out;
    float* outw = outp + (size_t)N * 128;

    cudaFuncSetAttribute(vsn_stage1, cudaFuncAttributeMaxDynamicSharedMemorySize, 73472);
    cudaFuncSetAttribute(vsn_stage2, cudaFuncAttributeMaxDynamicSharedMemorySize, 84480);

    dim3 g1(tiles, 16);
    vsn_stage1<<<g1, 256, 73472>>>(x, W1, b1, W2, b2, Wg, bg, Ws, bs, gamma, beta);
    vsn_stage2<<<tiles, 256, 84480>>>(sW1, sb1, sW2, sb2, sWg, sbg, sWs, sbs,
                                      sgamma, sbeta, outp, outw);
}

// round 7
// speedup vs baseline: 1.0011x; 1.0009x over previous
#include <cuda_runtime.h>
#include <math.h>

#define NMAX 16384

// 128 MB scratch for stacked, stored block-transposed:
// stackedT[tile][k][r], tile = n/64, r = n%64, k = v*128 + o
__device__ __align__(256) float g_stackedT[(size_t)NMAX * 2048];

static __device__ __forceinline__ float eluf(float t) { return t > 0.f ? t : expm1f(t); }
static __device__ __forceinline__ float sigm(float t) { return 1.f / (1.f + expf(-t)); }

// ---- packed f32x2 helpers (sm_100+) ----
static __device__ __forceinline__ unsigned long long pk2(float lo, float hi) {
    unsigned long long r;
    asm("mov.b64 %0, {%1, %2};" : "=l"(r) : "f"(lo), "f"(hi));
    return r;
}
static __device__ __forceinline__ void upk2(unsigned long long p, float& lo, float& hi) {
    asm("mov.b64 {%0, %1}, %2;" : "=f"(lo), "=f"(hi) : "l"(p));
}
static __device__ __forceinline__ void fma2(unsigned long long& d,
                                            unsigned long long a,
                                            unsigned long long b) {
    asm("fma.rn.f32x2 %0, %1, %2, %0;" : "+l"(d) : "l"(a), "l"(b));
}

// ---------------------------------------------------------------------------
// Stage 1: per-variable GRN + LayerNorm -> g_stackedT
// grid = (N/64, 16), 256 threads, 3 CTAs/SM (71.8 KB smem).
// Thread tile: 8 rows (rt = tid&7) x 1 output per 32-o chunk (ot = tid>>3).
// ---------------------------------------------------------------------------
__global__ void __launch_bounds__(256, 3) vsn_stage1(
    const float* __restrict__ x,
    const float* __restrict__ W1, const float* __restrict__ b1,
    const float* __restrict__ W2, const float* __restrict__ b2,
    const float* __restrict__ Wg, const float* __restrict__ bg,
    const float* __restrict__ Ws, const float* __restrict__ bs,
    const float* __restrict__ gamma, const float* __restrict__ beta)
{
    extern __shared__ float sm[];
    float* sh_h  = sm;            // [128][68]  h transposed: [d][r]
    float* sh_w2 = sm + 8704;     // [32][132]
    float* sh_wg = sm + 12928;    // [32][132]
    float* sh_ps = sm + 17152;    // [8][64] partial sums
    float* sh_q  = sm + 17664;    // [8][64] partial sumsq
    float* smean = sm + 18176;    // [64]
    float* srstd = sm + 18240;    // [64]
    float* sx    = sm + 18304;    // [64]
    // total 18368 floats = 73472 B

    const int tid = threadIdx.x;
    const int rt  = tid & 7;       // rows rt*8 .. rt*8+7
    const int ot  = tid >> 3;      // 0..31 ; o = oc + ot
    const int wrp = tid >> 5;
    const int v   = blockIdx.y;
    const int r0  = blockIdx.x * 64;

    for (int i = tid; i < 64; i += 256) sx[i] = x[(size_t)(r0 + i) * 16 + v];
    __syncthreads();

    // h[d][r] = elu(x[r]*W1[v,d] + b1[v,d])
    {
        const float* W1v = W1 + v * 128;
        const float* b1v = b1 + v * 128;
        for (int idx = tid; idx < 8192; idx += 256) {
            int r = idx & 63, d = idx >> 6;
            sh_h[d * 68 + r] = eluf(fmaf(sx[r], W1v[d], b1v[d]));
        }
    }

    float y[4][8];   // y[chunk][p]: o = chunk*32 + ot, row = rt*8+p

    for (int oc = 0; oc < 128; oc += 32) {
        __syncthreads();
        const float* W2b = W2 + ((size_t)v * 128 + oc) * 128;
        const float* Wgb = Wg + ((size_t)v * 128 + oc) * 128;
        for (int idx = tid; idx < 1024; idx += 256) {
            int o = idx >> 5, dq = (idx & 31) * 4;
            float4 a = *(const float4*)(W2b + o * 128 + dq);
            float* p = sh_w2 + o * 132 + dq;
            p[0] = a.x; p[1] = a.y; p[2] = a.z; p[3] = a.w;
            float4 b = *(const float4*)(Wgb + o * 128 + dq);
            float* q = sh_wg + o * 132 + dq;
            q[0] = b.x; q[1] = b.y; q[2] = b.z; q[3] = b.w;
        }
        __syncthreads();

        unsigned long long a2[4], ag[4];
        #pragma unroll
        for (int q = 0; q < 4; q++) { a2[q] = 0ull; ag[q] = 0ull; }

        const float* hrow = sh_h + rt * 8;
        const float* w2row = sh_w2 + ot * 132;
        const float* wgrow = sh_wg + ot * 132;
        #pragma unroll 4
        for (int d = 0; d < 128; d++) {
            ulonglong2 h01 = *(const ulonglong2*)(hrow + d * 68);
            ulonglong2 h23 = *(const ulonglong2*)(hrow + d * 68 + 4);
            float w2v = w2row[d];
            unsigned long long w2p = pk2(w2v, w2v);
            fma2(a2[0], h01.x, w2p);
            fma2(a2[1], h01.y, w2p);
            fma2(a2[2], h23.x, w2p);
            fma2(a2[3], h23.y, w2p);
            float wgv = wgrow[d];
            unsigned long long wgp = pk2(wgv, wgv);
            fma2(ag[0], h01.x, wgp);
            fma2(ag[1], h01.y, wgp);
            fma2(ag[2], h23.x, wgp);
            fma2(ag[3], h23.y, wgp);
        }

        // epilogue into registers
        {
            int o = oc + ot;
            int slot = oc >> 5;
            float b2v = b2[v * 128 + o];
            float bgv = bg[v * 128 + o];
            float wsv = Ws[v * 128 + o];
            float bsv = bs[v * 128 + o];
            #pragma unroll
            for (int q = 0; q < 4; q++) {
                float h2a, h2b, ga, gb;
                upk2(a2[q], h2a, h2b);
                upk2(ag[q], ga, gb);
                int p = q * 2;
                float g0 = sigm(ga + bgv);
                float g1 = sigm(gb + bgv);
                float sk0 = fmaf(sx[rt * 8 + p], wsv, bsv);
                float sk1 = fmaf(sx[rt * 8 + p + 1], wsv, bsv);
                y[slot][p]     = g0 * (h2a + b2v) + (1.f - g0) * sk0;
                y[slot][p + 1] = g1 * (h2b + b2v) + (1.f - g1) * sk1;
            }
        }
    }

    // LayerNorm partials: per-thread over its 4 o-values per row
    {
        float s[8], s2[8];
        #pragma unroll
        for (int p = 0; p < 8; p++) {
            float a = y[0][p] + y[1][p];
            float b = y[2][p] + y[3][p];
            s[p] = a + b;
            s2[p] = y[0][p] * y[0][p];
            s2[p] = fmaf(y[1][p], y[1][p], s2[p]);
            s2[p] = fmaf(y[2][p], y[2][p], s2[p]);
            s2[p] = fmaf(y[3][p], y[3][p], s2[p]);
        }
        #pragma unroll
        for (int p = 0; p < 8; p++) {
            s[p]  += __shfl_xor_sync(0xffffffffu, s[p], 8);
            s[p]  += __shfl_xor_sync(0xffffffffu, s[p], 16);
            s2[p] += __shfl_xor_sync(0xffffffffu, s2[p], 8);
            s2[p] += __shfl_xor_sync(0xffffffffu, s2[p], 16);
        }
        if ((ot & 3) == 0) {
            #pragma unroll
            for (int p = 0; p < 8; p++) {
                sh_ps[wrp * 64 + rt * 8 + p] = s[p];
                sh_q[wrp * 64 + rt * 8 + p] = s2[p];
            }
        }
    }
    __syncthreads();
    if (tid < 64) {
        float s = 0.f, s2 = 0.f;
        #pragma unroll
        for (int w = 0; w < 8; w++) { s += sh_ps[w * 64 + tid]; s2 += sh_q[w * 64 + tid]; }
        float m = s * 0.0078125f;
        float var = fmaf(-m, m, s2 * 0.0078125f);
        smean[tid] = m;
        srstd[tid] = rsqrtf(var + 1e-5f);
    }
    __syncthreads();

    // normalize in registers + write transposed to global
    {
        float mrow[8], rrow[8];
        #pragma unroll
        for (int p = 0; p < 8; p++) { mrow[p] = smean[rt * 8 + p]; rrow[p] = srstd[rt * 8 + p]; }
        float* dst = g_stackedT + ((size_t)blockIdx.x * 2048 + v * 128) * 64;
        const float* gv = gamma + v * 128;
        const float* bv = beta + v * 128;
        #pragma unroll
        for (int slot = 0; slot < 4; slot++) {
            int o = slot * 32 + ot;
            float go = gv[o], bo = bv[o];
            float4 oa, ob;
            oa.x = fmaf((y[slot][0] - mrow[0]) * rrow[0], go, bo);
            oa.y = fmaf((y[slot][1] - mrow[1]) * rrow[1], go, bo);
            oa.z = fmaf((y[slot][2] - mrow[2]) * rrow[2], go, bo);
            oa.w = fmaf((y[slot][3] - mrow[3]) * rrow[3], go, bo);
            ob.x = fmaf((y[slot][4] - mrow[4]) * rrow[4], go, bo);
            ob.y = fmaf((y[slot][5] - mrow[5]) * rrow[5], go, bo);
            ob.z = fmaf((y[slot][6] - mrow[6]) * rrow[6], go, bo);
            ob.w = fmaf((y[slot][7] - mrow[7]) * rrow[7], go, bo);
            *(float4*)(dst + o * 64 + rt * 8) = oa;
            *(float4*)(dst + o * 64 + rt * 8 + 4) = ob;
        }
    }
}

// ---------------------------------------------------------------------------
// Stage 2: softmax GRN + weighted sum. grid = N/64, 256 threads, 2 CTAs/SM.
// Thread tile: 8 rows (rt = tid&7) x 4 hs-outputs (jt = tid>>3, j = jt*4+i).
// K chunked by 64 (32 chunks) to shrink smem to 84.5 KB.
// ---------------------------------------------------------------------------
__global__ void __launch_bounds__(256, 2) vsn_stage2(
    const float* __restrict__ sW1, const float* __restrict__ sb1,
    const float* __restrict__ sW2, const float* __restrict__ sb2,
    const float* __restrict__ sWg, const float* __restrict__ sbg,
    const float* __restrict__ sWs, const float* __restrict__ sbs,
    const float* __restrict__ sgamma, const float* __restrict__ sbeta,
    float* __restrict__ outp, float* __restrict__ outw)
{
    extern __shared__ float sm[];
    float* sh_f  = sm;            // [64 k][64 r] flat chunk
    float* warea = sm + 4096;     // 12672 floats, multi-use
    float* sh_ws = sm + 16768;    // [16][68]
    float* sh_sk = sm + 17856;    // [64][17]
    float* sh_z  = sm + 18944;    // [64][17]
    float* sh_w  = sm + 20032;    // [64][17]
    // total 21120 floats = 84480 B

    float* sh_w1 = warea;           // [128][68] during main GEMM
    float* sh_hs = warea;           // [64][133]  after GEMM
    float* sh_s2 = warea + 8512;    // [16][130]
    float* sh_sg = warea + 10592;   // [16][130]
    float* sh_p3 = warea;           // [128][64]  pass-3 data
    float* sh_o  = warea;           // [64][132]  pass-3 output staging

    const int tid = threadIdx.x;
    const int rt = tid & 7;         // rows rt*8 .. rt*8+7
    const int jt = tid >> 3;        // 0..31 ; j = jt*4+i
    const int v16 = jt & 15;
    const int tile = blockIdx.x;
    const size_t rowbase = (size_t)tile * 64;
    const float* fbase = g_stackedT + (size_t)tile * 2048 * 64;

    unsigned long long acc[4][4];   // [i][rowpair]
    unsigned long long accs[4];
    #pragma unroll
    for (int i = 0; i < 4; i++) {
        accs[i] = 0ull;
        #pragma unroll
        for (int q = 0; q < 4; q++) acc[i][q] = 0ull;
    }

    // ---- main GEMM: hs (64x128) and sks (64x16) over K=2048 in 32 chunks ----
    for (int c = 0; c < 32; c++) {
        __syncthreads();
        {
            const float4* src = (const float4*)(fbase + (size_t)c * 64 * 64);
            float4* dst = (float4*)sh_f;
            for (int idx = tid; idx < 1024; idx += 256) dst[idx] = src[idx];
        }
        for (int idx = tid; idx < 2048; idx += 256) {
            int j = idx >> 4, kq = (idx & 15) * 4;
            float4 a = *(const float4*)(sW1 + (size_t)j * 2048 + c * 64 + kq);
            float* p = sh_w1 + j * 68 + kq;
            p[0] = a.x; p[1] = a.y; p[2] = a.z; p[3] = a.w;
        }
        for (int idx = tid; idx < 256; idx += 256) {
            int vv = idx >> 4, kq = (idx & 15) * 4;
            float4 a = *(const float4*)(sWs + (size_t)vv * 2048 + c * 64 + kq);
            float* p = sh_ws + vv * 68 + kq;
            p[0] = a.x; p[1] = a.y; p[2] = a.z; p[3] = a.w;
        }
        __syncthreads();

        const float* frow = sh_f + rt * 8;
        const float* wsrow = sh_ws + v16 * 68;
        #pragma unroll 4
        for (int kk = 0; kk < 64; kk++) {
            ulonglong2 f01 = *(const ulonglong2*)(frow + kk * 64);
            ulonglong2 f23 = *(const ulonglong2*)(frow + kk * 64 + 4);
            float wsv = wsrow[kk];
            unsigned long long wsp = pk2(wsv, wsv);
            fma2(accs[0], f01.x, wsp);
            fma2(accs[1], f01.y, wsp);
            fma2(accs[2], f23.x, wsp);
            fma2(accs[3], f23.y, wsp);
            #pragma unroll
            for (int i = 0; i < 4; i++) {
                float w = sh_w1[(jt * 4 + i) * 68 + kk];
                unsigned long long wp = pk2(w, w);
                fma2(acc[i][0], f01.x, wp);
                fma2(acc[i][1], f01.y, wp);
                fma2(acc[i][2], f23.x, wp);
                fma2(acc[i][3], f23.y, wp);
            }
        }
    }
    __syncthreads();   // sh_w1 reads done; safe to overlay

    // sks -> shared (only jt<16), hs (elu) -> shared
    if (jt < 16) {
        float sbsv = sbs[v16];
        #pragma unroll
        for (int q = 0; q < 4; q++) {
            float a, b;
            upk2(accs[q], a, b);
            sh_sk[(rt * 8 + q * 2) * 17 + v16] = a + sbsv;
            sh_sk[(rt * 8 + q * 2 + 1) * 17 + v16] = b + sbsv;
        }
    }
    #pragma unroll
    for (int i = 0; i < 4; i++) {
        int jj = jt * 4 + i;
        float bb = sb1[jj];
        #pragma unroll
        for (int q = 0; q < 4; q++) {
            float a, b;
            upk2(acc[i][q], a, b);
            sh_hs[(rt * 8 + q * 2) * 133 + jj] = eluf(a + bb);
            sh_hs[(rt * 8 + q * 2 + 1) * 133 + jj] = eluf(b + bb);
        }
    }
    for (int idx = tid; idx < 512; idx += 256) {
        int vv = idx >> 5, jq = (idx & 31) * 4;
        float4 a = *(const float4*)(sW2 + vv * 128 + jq);
        float* p = sh_s2 + vv * 130 + jq;
        p[0] = a.x; p[1] = a.y; p[2] = a.z; p[3] = a.w;
        float4 b = *(const float4*)(sWg + vv * 128 + jq);
        float* q = sh_sg + vv * 130 + jq;
        q[0] = b.x; q[1] = b.y; q[2] = b.z; q[3] = b.w;
    }
    __syncthreads();

    // tiny GEMM 128 -> 16 (x2) and GRN combine: thread = (row, quarter of v's)
    {
        int q = tid & 3, r = tid >> 2;
        float a2[4] = {0.f, 0.f, 0.f, 0.f};
        float ag[4] = {0.f, 0.f, 0.f, 0.f};
        #pragma unroll 4
        for (int j = 0; j < 128; j++) {
            float hsv = sh_hs[r * 133 + j];
            #pragma unroll
            for (int i = 0; i < 4; i++) {
                a2[i] = fmaf(hsv, sh_s2[(q * 4 + i) * 130 + j], a2[i]);
                ag[i] = fmaf(hsv, sh_sg[(q * 4 + i) * 130 + j], ag[i]);
            }
        }
        #pragma unroll
        for (int i = 0; i < 4; i++) {
            int vv = q * 4 + i;
            float h2s = a2[i] + sb2[vv];
            float gs = sigm(ag[i] + sbg[vv]);
            float sk = sh_sk[r * 17 + vv];
            sh_z[r * 17 + vv] = gs * h2s + (1.f - gs) * sk;
        }
    }
    __syncthreads();

    // LN over 16 + softmax, one thread per row
    if (tid < 64) {
        float zz[16];
        float s = 0.f;
        #pragma unroll
        for (int vv = 0; vv < 16; vv++) { zz[vv] = sh_z[tid * 17 + vv]; s += zz[vv]; }
        float m = s * 0.0625f;
        float s2 = 0.f;
        #pragma unroll
        for (int vv = 0; vv < 16; vv++) { float d = zz[vv] - m; s2 = fmaf(d, d, s2); }
        float rstd = rsqrtf(s2 * 0.0625f + 1e-5f);
        float mx = -3.4e38f;
        #pragma unroll
        for (int vv = 0; vv < 16; vv++) {
            zz[vv] = fmaf((zz[vv] - m) * rstd, sgamma[vv], sbeta[vv]);
            mx = fmaxf(mx, zz[vv]);
        }
        float se = 0.f;
        #pragma unroll
        for (int vv = 0; vv < 16; vv++) { zz[vv] = expf(zz[vv] - mx); se += zz[vv]; }
        float inv = 1.f / se;
        #pragma unroll
        for (int vv = 0; vv < 16; vv++) sh_w[tid * 17 + vv] = zz[vv] * inv;
    }
    __syncthreads();

    // weights out (coalesced)
    for (int idx = tid; idx < 1024; idx += 256) {
        int r = idx >> 4, vv = idx & 15;
        outw[(rowbase + r) * 16 + vv] = sh_w[r * 17 + vv];
    }

    // ---- pass 3: processed[r][d] = sum_v stacked[r][v][d] * w[r][v] ----
    unsigned long long accp[4][4];
    #pragma unroll
    for (int i = 0; i < 4; i++)
        #pragma unroll
        for (int q = 0; q < 4; q++) accp[i][q] = 0ull;

    for (int vv = 0; vv < 16; vv++) {
        __syncthreads();
        {
            const float4* src = (const float4*)(fbase + (size_t)vv * 128 * 64);
            float4* dst = (float4*)sh_p3;
            for (int idx = tid; idx < 2048; idx += 256) dst[idx] = src[idx];
        }
        __syncthreads();
        unsigned long long wp[4];
        #pragma unroll
        for (int q = 0; q < 4; q++)
            wp[q] = pk2(sh_w[(rt * 8 + q * 2) * 17 + vv],
                        sh_w[(rt * 8 + q * 2 + 1) * 17 + vv]);
        #pragma unroll
        for (int i = 0; i < 4; i++) {
            const float* fp = sh_p3 + (jt * 4 + i) * 64 + rt * 8;
            ulonglong2 f01 = *(const ulonglong2*)fp;
            ulonglong2 f23 = *(const ulonglong2*)(fp + 4);
            fma2(accp[i][0], f01.x, wp[0]);
            fma2(accp[i][1], f01.y, wp[1]);
            fma2(accp[i][2], f23.x, wp[2]);
            fma2(accp[i][3], f23.y, wp[3]);
        }
    }
    __syncthreads();
    #pragma unroll
    for (int i = 0; i < 4; i++) {
        int d = jt * 4 + i;
        #pragma unroll
        for (int q = 0; q < 4; q++) {
            float a, b;
            upk2(accp[i][q], a, b);
            sh_o[(rt * 8 + q * 2) * 132 + d] = a;
            sh_o[(rt * 8 + q * 2 + 1) * 132 + d] = b;
        }
    }
    __syncthreads();
    for (int idx = tid; idx < 2048; idx += 256) {
        int r = idx >> 5, dq = (idx & 31) * 4;
        float4 a = *(const float4*)(sh_o + r * 132 + dq);
        *(float4*)(outp + (rowbase + r) * 128 + dq) = a;
    }
}

// ---------------------------------------------------------------------------
extern "C" void kernel_launch(void* const* d_in, const int* in_sizes, int n_in,
                              void* d_out, int out_size) {
    const float* x      = (const float*)d_in[0];
    const float* W1     = (const float*)d_in[1];
    const float* b1     = (const float*)d_in[2];
    const float* W2     = (const float*)d_in[3];
    const float* b2     = (const float*)d_in[4];
    const float* Wg     = (const float*)d_in[5];
    const float* bg     = (const float*)d_in[6];
    const float* Ws     = (const float*)d_in[7];
    const float* bs     = (const float*)d_in[8];
    const float* gamma  = (const float*)d_in[9];
    const float* beta   = (const float*)d_in[10];
    const float* sW1    = (const float*)d_in[11];
    const float* sb1    = (const float*)d_in[12];
    const float* sW2    = (const float*)d_in[13];
    const float* sb2    = (const float*)d_in[14];
    const float* sWg    = (const float*)d_in[15];
    const float* sbg    = (const float*)d_in[16];
    const float* sWs    = (const float*)d_in[17];
    const float* sbs    = (const float*)d_in[18];
    const float* sgamma = (const float*)d_in[19];
    const float* sbeta  = (const float*)d_in[20];

    int N = in_sizes[0] / 16;          // 16384 rows
    int tiles = N / 64;                // 256

    float* outp = (float*)d_out;
    float* outw = outp + (size_t)N * 128;

    cudaFuncSetAttribute(vsn_stage1, cudaFuncAttributeMaxDynamicSharedMemorySize, 73472);
    cudaFuncSetAttribute(vsn_stage2, cudaFuncAttributeMaxDynamicSharedMemorySize, 84480);

    dim3 g1(tiles, 16);
    vsn_stage1<<<g1, 256, 73472>>>(x, W1, b1, W2, b2, Wg, bg, Ws, bs, gamma, beta);
    vsn_stage2<<<tiles, 256, 84480>>>(sW1, sb1, sW2, sb2, sWg, sbg, sWs, sbs,
                                      sgamma, sbeta, outp, outw);
}

// round 9
// speedup vs baseline: 1.3624x; 1.3610x over previous
#include <cuda_runtime.h>
#include <cstdint>
#include <math.h>

#define NMAX 16384
__device__ __align__(256) float g_stackedT[(size_t)NMAX * 2048];

static __device__ __forceinline__ float eluf(float t) { return t > 0.f ? t : expm1f(t); }
static __device__ __forceinline__ float sigm(float t) { return 1.f / (1.f + expf(-t)); }

// tf32 split: both halves tf32-rounded (valid mma operands)
static __device__ __forceinline__ void split2(float x, float& hi, float& lo) {
    uint32_t t;
    asm("cvt.rna.tf32.f32 %0, %1;" : "=r"(t) : "f"(x));
    hi = __uint_as_float(t);
    float l = x - hi;
    asm("cvt.rna.tf32.f32 %0, %1;" : "=r"(t) : "f"(l));
    lo = __uint_as_float(t);
}
static __device__ __forceinline__ void mma8(float* c, const uint32_t* a,
                                            uint32_t b0, uint32_t b1) {
    asm volatile(
        "mma.sync.aligned.m16n8k8.row.col.f32.tf32.tf32.f32 "
        "{%0,%1,%2,%3}, {%4,%5,%6,%7}, {%8,%9}, {%0,%1,%2,%3};"
        : "+f"(c[0]), "+f"(c[1]), "+f"(c[2]), "+f"(c[3])
        : "r"(a[0]), "r"(a[1]), "r"(a[2]), "r"(a[3]), "r"(b0), "r"(b1));
}
static __device__ __forceinline__ uint32_t fbits(float x) { return __float_as_uint(x); }

// ---------------------------------------------------------------------------
// Stage 1 (tf32 mma.sync, 3-term split): grid (N/128, 16), 256 threads.
// A = h (128x128), B = [W2;Wg] (256x128), C (128x256) in fragments.
// Warp w: m-pair mp=w&3 (rows 32mp..32mp+31), n-half nh=w>>2 (n 128nh..+127).
// ---------------------------------------------------------------------------
#define SM1_FLOATS 35200
__global__ void __launch_bounds__(256, 1) vsn_stage1(
    const float* __restrict__ x,
    const float* __restrict__ W1, const float* __restrict__ b1,
    const float* __restrict__ W2, const float* __restrict__ b2,
    const float* __restrict__ Wg, const float* __restrict__ bg,
    const float* __restrict__ Ws, const float* __restrict__ bs,
    const float* __restrict__ gamma, const float* __restrict__ beta)
{
    extern __shared__ float sm[];
    float* A_hi = sm;               // [128][36]
    float* A_lo = sm + 4608;
    float* B_hi = sm + 9216;        // [256][36]
    float* B_lo = sm + 18432;       // end 27648
    float* arr1 = sm;               // [128][133] overlay after GEMM (h2 / y)
    float* arr2 = sm + 17024;       // [128][133] gate
    float* par  = sm + 34048;       // b2,bg,Ws,bs,gamma,beta (128 each)
    float* sx   = sm + 34816;       // [128]
    float* pmean = sm + 34944;
    float* prstd = sm + 35072;

    const int tid = threadIdx.x, wid = tid >> 5, lane = tid & 31;
    const int mp = wid & 3, nh = wid >> 2;
    const int v = blockIdx.y;
    const int r0 = blockIdx.x * 128;

    if (tid < 128) {
        sx[tid] = x[(size_t)(r0 + tid) * 16 + v];
        int o = tid;
        par[o]       = b2[v * 128 + o];
        par[128 + o] = bg[v * 128 + o];
        par[256 + o] = Ws[v * 128 + o];
        par[384 + o] = bs[v * 128 + o];
        par[512 + o] = gamma[v * 128 + o];
        par[640 + o] = beta[v * 128 + o];
    }

    float cfr[2][16][4];
    #pragma unroll
    for (int mi = 0; mi < 2; mi++)
        #pragma unroll
        for (int nt = 0; nt < 16; nt++)
            #pragma unroll
            for (int q = 0; q < 4; q++) cfr[mi][nt][q] = 0.f;

    const int ar = lane >> 2, ac = lane & 3;

    for (int kc = 0; kc < 4; kc++) {     // K chunks of 32
        __syncthreads();
        // A = h chunk: elu(x*W1+b1), split
        const float* W1v = W1 + v * 128 + kc * 32;
        const float* b1v = b1 + v * 128 + kc * 32;
        for (int idx = tid; idx < 4096; idx += 256) {
            int r = idx & 127, d = idx >> 7;
            float h = eluf(fmaf(sx[r], W1v[d], b1v[d]));
            float hi, lo;
            split2(h, hi, lo);
            A_hi[r * 36 + d] = hi;
            A_lo[r * 36 + d] = lo;
        }
        // B = [W2;Wg] chunk, split
        for (int idx = tid; idx < 2048; idx += 256) {
            int n = idx >> 3, kq = (idx & 7) * 4;
            const float* src = (n < 128)
                ? W2 + ((size_t)v * 128 + n) * 128 + kc * 32 + kq
                : Wg + ((size_t)v * 128 + (n - 128)) * 128 + kc * 32 + kq;
            float4 a = *(const float4*)src;
            float4 h4, l4;
            split2(a.x, h4.x, l4.x); split2(a.y, h4.y, l4.y);
            split2(a.z, h4.z, l4.z); split2(a.w, h4.w, l4.w);
            *(float4*)(B_hi + n * 36 + kq) = h4;
            *(float4*)(B_lo + n * 36 + kq) = l4;
        }
        __syncthreads();

        for (int ks = 0; ks < 4; ks++) {
            const int k0 = ks * 8;
            uint32_t aH[2][4], aL[2][4];
            #pragma unroll
            for (int mi = 0; mi < 2; mi++) {
                int rb = (mp * 32 + mi * 16 + ar) * 36 + k0 + ac;
                aH[mi][0] = fbits(A_hi[rb]);
                aH[mi][1] = fbits(A_hi[rb + 8 * 36]);
                aH[mi][2] = fbits(A_hi[rb + 4]);
                aH[mi][3] = fbits(A_hi[rb + 8 * 36 + 4]);
                aL[mi][0] = fbits(A_lo[rb]);
                aL[mi][1] = fbits(A_lo[rb + 8 * 36]);
                aL[mi][2] = fbits(A_lo[rb + 4]);
                aL[mi][3] = fbits(A_lo[rb + 8 * 36 + 4]);
            }
            #pragma unroll
            for (int nt = 0; nt < 16; nt++) {
                int nb = (nh * 128 + nt * 8 + ar) * 36 + k0 + ac;
                uint32_t bH0 = fbits(B_hi[nb]), bH1 = fbits(B_hi[nb + 4]);
                uint32_t bL0 = fbits(B_lo[nb]), bL1 = fbits(B_lo[nb + 4]);
                mma8(cfr[0][nt], aH[0], bH0, bH1);
                mma8(cfr[1][nt], aH[1], bH0, bH1);
                mma8(cfr[0][nt], aL[0], bH0, bH1);
                mma8(cfr[1][nt], aL[1], bH0, bH1);
                mma8(cfr[0][nt], aH[0], bL0, bL1);
                mma8(cfr[1][nt], aH[1], bL0, bL1);
            }
        }
    }
    __syncthreads();

    // frags -> arr1 (h2+b2) / arr2 (sigmoid gate). nh=0 -> W2 half, nh=1 -> Wg.
    {
        const int ac2 = (lane & 3) * 2;
        #pragma unroll
        for (int mi = 0; mi < 2; mi++) {
            #pragma unroll
            for (int half = 0; half < 2; half++) {
                int r = mp * 32 + mi * 16 + ar + half * 8;
                #pragma unroll
                for (int nt = 0; nt < 16; nt++) {
                    int n = nt * 8 + ac2;
                    float v0 = cfr[mi][nt][half * 2];
                    float v1 = cfr[mi][nt][half * 2 + 1];
                    if (nh == 0) {
                        arr1[r * 133 + n]     = v0 + par[n];
                        arr1[r * 133 + n + 1] = v1 + par[n + 1];
                    } else {
                        arr2[r * 133 + n]     = sigm(v0 + par[128 + n]);
                        arr2[r * 133 + n + 1] = sigm(v1 + par[128 + n + 1]);
                    }
                }
            }
        }
    }
    __syncthreads();

    // gate/skip combine + LN stats, one thread per row
    if (tid < 128) {
        int r = tid;
        float xr = sx[r];
        float s = 0.f, s2 = 0.f;
        for (int o = 0; o < 128; o++) {
            float h2 = arr1[r * 133 + o];
            float g  = arr2[r * 133 + o];
            float sk = fmaf(xr, par[256 + o], par[384 + o]);
            float yv = g * h2 + (1.f - g) * sk;
            arr1[r * 133 + o] = yv;
            s += yv;
            s2 = fmaf(yv, yv, s2);
        }
        float m = s * 0.0078125f;
        pmean[r] = m;
        prstd[r] = rsqrtf(fmaf(-m, m, s2 * 0.0078125f) + 1e-5f);
    }
    __syncthreads();

    // normalize + transposed write (64-row tile layout)
    {
        float* dst0 = g_stackedT + ((size_t)(blockIdx.x * 2) * 2048 + v * 128) * 64;
        for (int idx = tid; idx < 16384; idx += 256) {
            int o = idx >> 7, r = idx & 127;
            float val = fmaf((arr1[r * 133 + o] - pmean[r]) * prstd[r],
                             par[512 + o], par[640 + o]);
            dst0[(size_t)(r >> 6) * 2048 * 64 + o * 64 + (r & 63)] = val;
        }
    }
}

// ---------------------------------------------------------------------------
// Stage 2: R3 scalar kernel verbatim (421 us measured). grid N/64, 256 thr.
// ---------------------------------------------------------------------------
__global__ void __launch_bounds__(256) vsn_stage2(
    const float* __restrict__ sW1, const float* __restrict__ sb1,
    const float* __restrict__ sW2, const float* __restrict__ sb2,
    const float* __restrict__ sWg, const float* __restrict__ sbg,
    const float* __restrict__ sWs, const float* __restrict__ sbs,
    const float* __restrict__ sgamma, const float* __restrict__ sbeta,
    float* __restrict__ outp, float* __restrict__ outw)
{
    extern __shared__ float sm[];
    float* sh_f  = sm;
    float* warea = sm + 8192;
    float* sh_ws = sm + 25216;
    float* sh_sk = sm + 27328;
    float* sh_z  = sm + 28416;
    float* sh_w  = sm + 29504;
    float* sh_w1 = warea;
    float* sh_hs = warea;
    float* sh_s2 = warea + 8512;
    float* sh_sg = warea + 10592;
    float* sh_o  = warea;

    const int tid = threadIdx.x;
    const int rt = tid & 15, jt = tid >> 4;
    const int tile = blockIdx.x;
    const size_t rowbase = (size_t)tile * 64;
    const float* fbase = g_stackedT + (size_t)tile * 2048 * 64;

    float acc[32], accs[4];
    #pragma unroll
    for (int i = 0; i < 32; i++) acc[i] = 0.f;
    accs[0] = accs[1] = accs[2] = accs[3] = 0.f;

    for (int c = 0; c < 16; c++) {
        __syncthreads();
        {
            const float4* src = (const float4*)(fbase + (size_t)c * 128 * 64);
            float4* dst = (float4*)sh_f;
            for (int idx = tid; idx < 2048; idx += 256) dst[idx] = src[idx];
        }
        for (int idx = tid; idx < 4096; idx += 256) {
            int j = idx >> 5, kq = (idx & 31) * 4;
            float4 a = *(const float4*)(sW1 + (size_t)j * 2048 + c * 128 + kq);
            float* p = sh_w1 + j * 133 + kq;
            p[0] = a.x; p[1] = a.y; p[2] = a.z; p[3] = a.w;
        }
        for (int idx = tid; idx < 512; idx += 256) {
            int vv = idx >> 5, kq = (idx & 31) * 4;
            float4 a = *(const float4*)(sWs + (size_t)vv * 2048 + c * 128 + kq);
            float* p = sh_ws + vv * 132 + kq;
            p[0] = a.x; p[1] = a.y; p[2] = a.z; p[3] = a.w;
        }
        __syncthreads();
        #pragma unroll 8
        for (int kk = 0; kk < 128; kk++) {
            float4 fv = *(const float4*)(sh_f + kk * 64 + rt * 4);
            float wsv = sh_ws[jt * 132 + kk];
            accs[0] = fmaf(fv.x, wsv, accs[0]);
            accs[1] = fmaf(fv.y, wsv, accs[1]);
            accs[2] = fmaf(fv.z, wsv, accs[2]);
            accs[3] = fmaf(fv.w, wsv, accs[3]);
            #pragma unroll
            for (int i = 0; i < 8; i++) {
                float w = sh_w1[(jt * 8 + i) * 133 + kk];
                acc[0 * 8 + i] = fmaf(fv.x, w, acc[0 * 8 + i]);
                acc[1 * 8 + i] = fmaf(fv.y, w, acc[1 * 8 + i]);
                acc[2 * 8 + i] = fmaf(fv.z, w, acc[2 * 8 + i]);
                acc[3 * 8 + i] = fmaf(fv.w, w, acc[3 * 8 + i]);
            }
        }
    }
    __syncthreads();

    #pragma unroll
    for (int j = 0; j < 4; j++)
        sh_sk[(rt * 4 + j) * 17 + jt] = accs[j] + sbs[jt];
    #pragma unroll
    for (int i = 0; i < 8; i++) {
        int jj = jt * 8 + i;
        float bb = sb1[jj];
        #pragma unroll
        for (int j = 0; j < 4; j++)
            sh_hs[(rt * 4 + j) * 133 + jj] = eluf(acc[j * 8 + i] + bb);
    }
    for (int idx = tid; idx < 512; idx += 256) {
        int vv = idx >> 5, jq = (idx & 31) * 4;
        float4 a = *(const float4*)(sW2 + vv * 128 + jq);
        float* p = sh_s2 + vv * 130 + jq;
        p[0] = a.x; p[1] = a.y; p[2] = a.z; p[3] = a.w;
        float4 b = *(const float4*)(sWg + vv * 128 + jq);
        float* q = sh_sg + vv * 130 + jq;
        q[0] = b.x; q[1] = b.y; q[2] = b.z; q[3] = b.w;
    }
    __syncthreads();
    {
        int q = tid & 3, r = tid >> 2;
        float a2[4] = {0.f, 0.f, 0.f, 0.f};
        float ag[4] = {0.f, 0.f, 0.f, 0.f};
        #pragma unroll 4
        for (int j = 0; j < 128; j++) {
            float hsv = sh_hs[r * 133 + j];
            #pragma unroll
            for (int i = 0; i < 4; i++) {
                a2[i] = fmaf(hsv, sh_s2[(q * 4 + i) * 130 + j], a2[i]);
                ag[i] = fmaf(hsv, sh_sg[(q * 4 + i) * 130 + j], ag[i]);
            }
        }
        #pragma unroll
        for (int i = 0; i < 4; i++) {
            int vv = q * 4 + i;
            float h2s = a2[i] + sb2[vv];
            float gs = sigm(ag[i] + sbg[vv]);
            float sk = sh_sk[r * 17 + vv];
            sh_z[r * 17 + vv] = gs * h2s + (1.f - gs) * sk;
        }
    }
    __syncthreads();
    if (tid < 64) {
        float zz[16];
        float s = 0.f;
        #pragma unroll
        for (int vv = 0; vv < 16; vv++) { zz[vv] = sh_z[tid * 17 + vv]; s += zz[vv]; }
        float m = s * 0.0625f;
        float s2 = 0.f;
        #pragma unroll
        for (int vv = 0; vv < 16; vv++) { float d = zz[vv] - m; s2 = fmaf(d, d, s2); }
        float rstd = rsqrtf(s2 * 0.0625f + 1e-5f);
        float mx = -3.4e38f;
        #pragma unroll
        for (int vv = 0; vv < 16; vv++) {
            zz[vv] = fmaf((zz[vv] - m) * rstd, sgamma[vv], sbeta[vv]);
            mx = fmaxf(mx, zz[vv]);
        }
        float se = 0.f;
        #pragma unroll
        for (int vv = 0; vv < 16; vv++) { zz[vv] = expf(zz[vv] - mx); se += zz[vv]; }
        float inv = 1.f / se;
        #pragma unroll
        for (int vv = 0; vv < 16; vv++) sh_w[tid * 17 + vv] = zz[vv] * inv;
    }
    __syncthreads();
    for (int idx = tid; idx < 1024; idx += 256) {
        int r = idx >> 4, vv = idx & 15;
        outw[(rowbase + r) * 16 + vv] = sh_w[r * 17 + vv];
    }

    float accp[32];
    #pragma unroll
    for (int i = 0; i < 32; i++) accp[i] = 0.f;
    for (int vv = 0; vv < 16; vv++) {
        __syncthreads();
        {
            const float4* src = (const float4*)(fbase + (size_t)vv * 128 * 64);
            float4* dst = (float4*)sh_f;
            for (int idx = tid; idx < 2048; idx += 256) dst[idx] = src[idx];
        }
        __syncthreads();
        float wv0 = sh_w[(rt * 4 + 0) * 17 + vv];
        float wv1 = sh_w[(rt * 4 + 1) * 17 + vv];
        float wv2 = sh_w[(rt * 4 + 2) * 17 + vv];
        float wv3 = sh_w[(rt * 4 + 3) * 17 + vv];
        #pragma unroll
        for (int dd = 0; dd < 8; dd++) {
            float4 fv = *(const float4*)(sh_f + (jt * 8 + dd) * 64 + rt * 4);
            accp[0 * 8 + dd] = fmaf(fv.x, wv0, accp[0 * 8 + dd]);
            accp[1 * 8 + dd] = fmaf(fv.y, wv1, accp[1 * 8 + dd]);
            accp[2 * 8 + dd] = fmaf(fv.z, wv2, accp[2 * 8 + dd]);
            accp[3 * 8 + dd] = fmaf(fv.w, wv3, accp[3 * 8 + dd]);
        }
    }
    __syncthreads();
    #pragma unroll
    for (int j = 0; j < 4; j++)
        #pragma unroll
        for (int dd = 0; dd < 8; dd++)
            sh_o[(rt * 4 + j) * 132 + jt * 8 + dd] = accp[j * 8 + dd];
    __syncthreads();
    for (int idx = tid; idx < 2048; idx += 256) {
        int r = idx >> 5, dq = (idx & 31) * 4;
        float4 a = *(const float4*)(sh_o + r * 132 + dq);
        *(float4*)(outp + (rowbase + r) * 128 + dq) = a;
    }
}

extern "C" void kernel_launch(void* const* d_in, const int* in_sizes, int n_in,
                              void* d_out, int out_size) {
    const float* x      = (const float*)d_in[0];
    const float* W1     = (const float*)d_in[1];
    const float* b1     = (const float*)d_in[2];
    const float* W2     = (const float*)d_in[3];
    const float* b2     = (const float*)d_in[4];
    const float* Wg     = (const float*)d_in[5];
    const float* bg     = (const float*)d_in[6];
    const float* Ws     = (const float*)d_in[7];
    const float* bs     = (const float*)d_in[8];
    const float* gamma  = (const float*)d_in[9];
    const float* beta   = (const float*)d_in[10];
    const float* sW1    = (const float*)d_in[11];
    const float* sb1    = (const float*)d_in[12];
    const float* sW2    = (const float*)d_in[13];
    const float* sb2    = (const float*)d_in[14];
    const float* sWg    = (const float*)d_in[15];
    const float* sbg    = (const float*)d_in[16];
    const float* sWs    = (const float*)d_in[17];
    const float* sbs    = (const float*)d_in[18];
    const float* sgamma = (const float*)d_in[19];
    const float* sbeta  = (const float*)d_in[20];

    int N = in_sizes[0] / 16;          // 16384
    int tiles64 = N / 64;              // 256
    int tiles128 = N / 128;            // 128

    float* outp = (float*)d_out;
    float* outw = outp + (size_t)N * 128;

    cudaFuncSetAttribute(vsn_stage1, cudaFuncAttributeMaxDynamicSharedMemorySize,
                         SM1_FLOATS * 4);
    cudaFuncSetAttribute(vsn_stage2, cudaFuncAttributeMaxDynamicSharedMemorySize, 122368);

    dim3 g1(tiles128, 16);
    vsn_stage1<<<g1, 256, SM1_FLOATS * 4>>>(x, W1, b1, W2, b2, Wg, bg, Ws, bs, gamma, beta);
    vsn_stage2<<<tiles64, 256, 122368>>>(sW1, sb1, sW2, sb2, sWg, sbg, sWs, sbs,
                                         sgamma, sbeta, outp, outw);
}

// round 10
// speedup vs baseline: 1.6767x; 1.2307x over previous
#include <cuda_runtime.h>
#include <cstdint>
#include <math.h>

#define NMAX 16384
__device__ __align__(256) float g_stackedT[(size_t)NMAX * 2048];

static __device__ __forceinline__ float eluf(float t) {
    return t > 0.f ? t : __expf(t) - 1.f;
}
static __device__ __forceinline__ float sigm(float t) {
    return __fdividef(1.f, 1.f + __expf(-t));
}

// tf32 split: both halves tf32-rounded (valid mma operands)
static __device__ __forceinline__ void split2(float x, float& hi, float& lo) {
    uint32_t t;
    asm("cvt.rna.tf32.f32 %0, %1;" : "=r"(t) : "f"(x));
    hi = __uint_as_float(t);
    float l = x - hi;
    asm("cvt.rna.tf32.f32 %0, %1;" : "=r"(t) : "f"(l));
    lo = __uint_as_float(t);
}
static __device__ __forceinline__ void mma8(float* c, const uint32_t* a,
                                            uint32_t b0, uint32_t b1) {
    asm volatile(
        "mma.sync.aligned.m16n8k8.row.col.f32.tf32.tf32.f32 "
        "{%0,%1,%2,%3}, {%4,%5,%6,%7}, {%8,%9}, {%0,%1,%2,%3};"
        : "+f"(c[0]), "+f"(c[1]), "+f"(c[2]), "+f"(c[3])
        : "r"(a[0]), "r"(a[1]), "r"(a[2]), "r"(a[3]), "r"(b0), "r"(b1));
}
static __device__ __forceinline__ uint32_t fbits(float x) { return __float_as_uint(x); }

// ---------------------------------------------------------------------------
// Stage 1 (tf32 mma.sync, 3-term split): grid (N/128, 16), 256 threads.
// A = h (128x128), B = [W2;Wg] (256x128), C (128x256) in fragments.
// ---------------------------------------------------------------------------
#define SM1_FLOATS 35712
__global__ void __launch_bounds__(256, 1) vsn_stage1(
    const float* __restrict__ x,
    const float* __restrict__ W1, const float* __restrict__ b1,
    const float* __restrict__ W2, const float* __restrict__ b2,
    const float* __restrict__ Wg, const float* __restrict__ bg,
    const float* __restrict__ Ws, const float* __restrict__ bs,
    const float* __restrict__ gamma, const float* __restrict__ beta)
{
    extern __shared__ float sm[];
    float* A_hi = sm;               // [128][36]
    float* A_lo = sm + 4608;
    float* B_hi = sm + 9216;        // [256][36]
    float* B_lo = sm + 18432;       // end 27648
    float* arr1 = sm;               // [128][133] overlay after GEMM (h2 / y)
    float* arr2 = sm + 17024;       // [128][133] gate
    float* par  = sm + 34048;       // b2,bg,Ws,bs,gamma,beta (128 each)
    float* sx   = sm + 34816;       // [128]
    float* pmean = sm + 34944;
    float* prstd = sm + 35072;
    float* part_s = sm + 35200;     // [2][128]
    float* part_q = sm + 35456;     // [2][128]

    const int tid = threadIdx.x, wid = tid >> 5, lane = tid & 31;
    const int mp = wid & 3, nh = wid >> 2;
    const int v = blockIdx.y;
    const int r0 = blockIdx.x * 128;

    if (tid < 128) {
        sx[tid] = x[(size_t)(r0 + tid) * 16 + v];
        int o = tid;
        par[o]       = b2[v * 128 + o];
        par[128 + o] = bg[v * 128 + o];
        par[256 + o] = Ws[v * 128 + o];
        par[384 + o] = bs[v * 128 + o];
        par[512 + o] = gamma[v * 128 + o];
        par[640 + o] = beta[v * 128 + o];
    }

    float cfr[2][16][4];
    #pragma unroll
    for (int mi = 0; mi < 2; mi++)
        #pragma unroll
        for (int nt = 0; nt < 16; nt++)
            #pragma unroll
            for (int q = 0; q < 4; q++) cfr[mi][nt][q] = 0.f;

    const int ar = lane >> 2, ac = lane & 3;

    for (int kc = 0; kc < 4; kc++) {     // K chunks of 32
        __syncthreads();
        const float* W1v = W1 + v * 128 + kc * 32;
        const float* b1v = b1 + v * 128 + kc * 32;
        for (int idx = tid; idx < 4096; idx += 256) {
            int r = idx & 127, d = idx >> 7;
            float h = eluf(fmaf(sx[r], W1v[d], b1v[d]));
            float hi, lo;
            split2(h, hi, lo);
            A_hi[r * 36 + d] = hi;
            A_lo[r * 36 + d] = lo;
        }
        for (int idx = tid; idx < 2048; idx += 256) {
            int n = idx >> 3, kq = (idx & 7) * 4;
            const float* src = (n < 128)
                ? W2 + ((size_t)v * 128 + n) * 128 + kc * 32 + kq
                : Wg + ((size_t)v * 128 + (n - 128)) * 128 + kc * 32 + kq;
            float4 a = *(const float4*)src;
            float4 h4, l4;
            split2(a.x, h4.x, l4.x); split2(a.y, h4.y, l4.y);
            split2(a.z, h4.z, l4.z); split2(a.w, h4.w, l4.w);
            *(float4*)(B_hi + n * 36 + kq) = h4;
            *(float4*)(B_lo + n * 36 + kq) = l4;
        }
        __syncthreads();

        for (int ks = 0; ks < 4; ks++) {
            const int k0 = ks * 8;
            uint32_t aH[2][4], aL[2][4];
            #pragma unroll
            for (int mi = 0; mi < 2; mi++) {
                int rb = (mp * 32 + mi * 16 + ar) * 36 + k0 + ac;
                aH[mi][0] = fbits(A_hi[rb]);
                aH[mi][1] = fbits(A_hi[rb + 8 * 36]);
                aH[mi][2] = fbits(A_hi[rb + 4]);
                aH[mi][3] = fbits(A_hi[rb + 8 * 36 + 4]);
                aL[mi][0] = fbits(A_lo[rb]);
                aL[mi][1] = fbits(A_lo[rb + 8 * 36]);
                aL[mi][2] = fbits(A_lo[rb + 4]);
                aL[mi][3] = fbits(A_lo[rb + 8 * 36 + 4]);
            }
            #pragma unroll
            for (int nt = 0; nt < 16; nt++) {
                int nb = (nh * 128 + nt * 8 + ar) * 36 + k0 + ac;
                uint32_t bH0 = fbits(B_hi[nb]), bH1 = fbits(B_hi[nb + 4]);
                uint32_t bL0 = fbits(B_lo[nb]), bL1 = fbits(B_lo[nb + 4]);
                mma8(cfr[0][nt], aH[0], bH0, bH1);
                mma8(cfr[1][nt], aH[1], bH0, bH1);
                mma8(cfr[0][nt], aL[0], bH0, bH1);
                mma8(cfr[1][nt], aL[1], bH0, bH1);
                mma8(cfr[0][nt], aH[0], bL0, bL1);
                mma8(cfr[1][nt], aH[1], bL0, bL1);
            }
        }
    }
    __syncthreads();

    // frags -> arr1 (h2+b2) / arr2 (sigmoid gate)
    {
        const int ac2 = (lane & 3) * 2;
        #pragma unroll
        for (int mi = 0; mi < 2; mi++) {
            #pragma unroll
            for (int half = 0; half < 2; half++) {
                int r = mp * 32 + mi * 16 + ar + half * 8;
                #pragma unroll
                for (int nt = 0; nt < 16; nt++) {
                    int n = nt * 8 + ac2;
                    float v0 = cfr[mi][nt][half * 2];
                    float v1 = cfr[mi][nt][half * 2 + 1];
                    if (nh == 0) {
                        arr1[r * 133 + n]     = v0 + par[n];
                        arr1[r * 133 + n + 1] = v1 + par[n + 1];
                    } else {
                        arr2[r * 133 + n]     = sigm(v0 + par[128 + n]);
                        arr2[r * 133 + n + 1] = sigm(v1 + par[128 + n + 1]);
                    }
                }
            }
        }
    }
    __syncthreads();

    // gate/skip combine + LN partials: thread = (row, half of o's)
    {
        int r = tid & 127, hf = tid >> 7;
        float xr = sx[r];
        float s = 0.f, s2 = 0.f;
        int o0 = hf * 64;
        for (int o = o0; o < o0 + 64; o++) {
            float h2 = arr1[r * 133 + o];
            float g  = arr2[r * 133 + o];
            float sk = fmaf(xr, par[256 + o], par[384 + o]);
            float yv = g * h2 + (1.f - g) * sk;
            arr1[r * 133 + o] = yv;
            s += yv;
            s2 = fmaf(yv, yv, s2);
        }
        part_s[hf * 128 + r] = s;
        part_q[hf * 128 + r] = s2;
    }
    __syncthreads();
    if (tid < 128) {
        float s  = part_s[tid] + part_s[128 + tid];
        float s2 = part_q[tid] + part_q[128 + tid];
        float m = s * 0.0078125f;
        pmean[tid] = m;
        prstd[tid] = rsqrtf(fmaf(-m, m, s2 * 0.0078125f) + 1e-5f);
    }
    __syncthreads();

    // normalize + transposed write (64-row tile layout)
    {
        float* dst0 = g_stackedT + ((size_t)(blockIdx.x * 2) * 2048 + v * 128) * 64;
        for (int idx = tid; idx < 16384; idx += 256) {
            int o = idx >> 7, r = idx & 127;
            float val = fmaf((arr1[r * 133 + o] - pmean[r]) * prstd[r],
                             par[512 + o], par[640 + o]);
            dst0[(size_t)(r >> 6) * 2048 * 64 + o * 64 + (r & 63)] = val;
        }
    }
}

// ---------------------------------------------------------------------------
// Stage 2: scalar R3 inner loop, K-chunk 64, 84.5 KB smem -> 2 CTAs/SM.
// grid N/64, 256 threads. rt = tid&15 (4 rows), jt = tid>>4 (8 j's).
// ---------------------------------------------------------------------------
__global__ void __launch_bounds__(256, 2) vsn_stage2(
    const float* __restrict__ sW1, const float* __restrict__ sb1,
    const float* __restrict__ sW2, const float* __restrict__ sb2,
    const float* __restrict__ sWg, const float* __restrict__ sbg,
    const float* __restrict__ sWs, const float* __restrict__ sbs,
    const float* __restrict__ sgamma, const float* __restrict__ sbeta,
    float* __restrict__ outp, float* __restrict__ outw)
{
    extern __shared__ float sm[];
    float* sh_f  = sm;            // [64 k][64 r]
    float* warea = sm + 4096;     // 12672 floats multi-use
    float* sh_ws = sm + 16768;    // [16][68]
    float* sh_sk = sm + 17856;    // [64][17]
    float* sh_z  = sm + 18944;    // [64][17]
    float* sh_w  = sm + 20032;    // [64][17]  -> total 21120 floats = 84480 B
    float* sh_w1 = warea;         // [128][68] during GEMM
    float* sh_hs = warea;         // [64][133] after
    float* sh_s2 = warea + 8512;  // [16][130]
    float* sh_sg = warea + 10592; // [16][130]
    float* sh_p3 = warea;         // [128][64] pass-3 tile
    float* sh_o  = warea;         // [64][132] output staging

    const int tid = threadIdx.x;
    const int rt = tid & 15, jt = tid >> 4;
    const int tile = blockIdx.x;
    const size_t rowbase = (size_t)tile * 64;
    const float* fbase = g_stackedT + (size_t)tile * 2048 * 64;

    float acc[32], accs[4];
    #pragma unroll
    for (int i = 0; i < 32; i++) acc[i] = 0.f;
    accs[0] = accs[1] = accs[2] = accs[3] = 0.f;

    for (int c = 0; c < 32; c++) {
        __syncthreads();
        {
            const float4* src = (const float4*)(fbase + (size_t)c * 64 * 64);
            float4* dst = (float4*)sh_f;
            for (int idx = tid; idx < 1024; idx += 256) dst[idx] = src[idx];
        }
        for (int idx = tid; idx < 2048; idx += 256) {
            int j = idx >> 4, kq = (idx & 15) * 4;
            float4 a = *(const float4*)(sW1 + (size_t)j * 2048 + c * 64 + kq);
            float* p = sh_w1 + j * 68 + kq;
            p[0] = a.x; p[1] = a.y; p[2] = a.z; p[3] = a.w;
        }
        if (tid < 256) {
            int idx = tid;
            if (idx < 256) {
                int vv = idx >> 4, kq = (idx & 15) * 4;
                float4 a = *(const float4*)(sWs + (size_t)vv * 2048 + c * 64 + kq);
                float* p = sh_ws + vv * 68 + kq;
                p[0] = a.x; p[1] = a.y; p[2] = a.z; p[3] = a.w;
            }
        }
        __syncthreads();
        #pragma unroll 8
        for (int kk = 0; kk < 64; kk++) {
            float4 fv = *(const float4*)(sh_f + kk * 64 + rt * 4);
            float wsv = sh_ws[jt * 68 + kk];
            accs[0] = fmaf(fv.x, wsv, accs[0]);
            accs[1] = fmaf(fv.y, wsv, accs[1]);
            accs[2] = fmaf(fv.z, wsv, accs[2]);
            accs[3] = fmaf(fv.w, wsv, accs[3]);
            #pragma unroll
            for (int i = 0; i < 8; i++) {
                float w = sh_w1[(jt * 8 + i) * 68 + kk];
                acc[0 * 8 + i] = fmaf(fv.x, w, acc[0 * 8 + i]);
                acc[1 * 8 + i] = fmaf(fv.y, w, acc[1 * 8 + i]);
                acc[2 * 8 + i] = fmaf(fv.z, w, acc[2 * 8 + i]);
                acc[3 * 8 + i] = fmaf(fv.w, w, acc[3 * 8 + i]);
            }
        }
    }
    __syncthreads();

    #pragma unroll
    for (int j = 0; j < 4; j++)
        sh_sk[(rt * 4 + j) * 17 + jt] = accs[j] + sbs[jt];
    #pragma unroll
    for (int i = 0; i < 8; i++) {
        int jj = jt * 8 + i;
        float bb = sb1[jj];
        #pragma unroll
        for (int j = 0; j < 4; j++)
            sh_hs[(rt * 4 + j) * 133 + jj] = eluf(acc[j * 8 + i] + bb);
    }
    for (int idx = tid; idx < 512; idx += 256) {
        int vv = idx >> 5, jq = (idx & 31) * 4;
        float4 a = *(const float4*)(sW2 + vv * 128 + jq);
        float* p = sh_s2 + vv * 130 + jq;
        p[0] = a.x; p[1] = a.y; p[2] = a.z; p[3] = a.w;
        float4 b = *(const float4*)(sWg + vv * 128 + jq);
        float* q = sh_sg + vv * 130 + jq;
        q[0] = b.x; q[1] = b.y; q[2] = b.z; q[3] = b.w;
    }
    __syncthreads();
    {
        int q = tid & 3, r = tid >> 2;
        float a2[4] = {0.f, 0.f, 0.f, 0.f};
        float ag[4] = {0.f, 0.f, 0.f, 0.f};
        #pragma unroll 4
        for (int j = 0; j < 128; j++) {
            float hsv = sh_hs[r * 133 + j];
            #pragma unroll
            for (int i = 0; i < 4; i++) {
                a2[i] = fmaf(hsv, sh_s2[(q * 4 + i) * 130 + j], a2[i]);
                ag[i] = fmaf(hsv, sh_sg[(q * 4 + i) * 130 + j], ag[i]);
            }
        }
        #pragma unroll
        for (int i = 0; i < 4; i++) {
            int vv = q * 4 + i;
            float h2s = a2[i] + sb2[vv];
            float gs = sigm(ag[i] + sbg[vv]);
            float sk = sh_sk[r * 17 + vv];
            sh_z[r * 17 + vv] = gs * h2s + (1.f - gs) * sk;
        }
    }
    __syncthreads();
    if (tid < 64) {
        float zz[16];
        float s = 0.f;
        #pragma unroll
        for (int vv = 0; vv < 16; vv++) { zz[vv] = sh_z[tid * 17 + vv]; s += zz[vv]; }
        float m = s * 0.0625f;
        float s2 = 0.f;
        #pragma unroll
        for (int vv = 0; vv < 16; vv++) { float d = zz[vv] - m; s2 = fmaf(d, d, s2); }
        float rstd = rsqrtf(s2 * 0.0625f + 1e-5f);
        float mx = -3.4e38f;
        #pragma unroll
        for (int vv = 0; vv < 16; vv++) {
            zz[vv] = fmaf((zz[vv] - m) * rstd, sgamma[vv], sbeta[vv]);
            mx = fmaxf(mx, zz[vv]);
        }
        float se = 0.f;
        #pragma unroll
        for (int vv = 0; vv < 16; vv++) { zz[vv] = __expf(zz[vv] - mx); se += zz[vv]; }
        float inv = __fdividef(1.f, se);
        #pragma unroll
        for (int vv = 0; vv < 16; vv++) sh_w[tid * 17 + vv] = zz[vv] * inv;
    }
    __syncthreads();
    for (int idx = tid; idx < 1024; idx += 256) {
        int r = idx >> 4, vv = idx & 15;
        outw[(rowbase + r) * 16 + vv] = sh_w[r * 17 + vv];
    }

    float accp[32];
    #pragma unroll
    for (int i = 0; i < 32; i++) accp[i] = 0.f;
    for (int vv = 0; vv < 16; vv++) {
        __syncthreads();
        {
            const float4* src = (const float4*)(fbase + (size_t)vv * 128 * 64);
            float4* dst = (float4*)sh_p3;
            for (int idx = tid; idx < 2048; idx += 256) dst[idx] = src[idx];
        }
        __syncthreads();
        float wv0 = sh_w[(rt * 4 + 0) * 17 + vv];
        float wv1 = sh_w[(rt * 4 + 1) * 17 + vv];
        float wv2 = sh_w[(rt * 4 + 2) * 17 + vv];
        float wv3 = sh_w[(rt * 4 + 3) * 17 + vv];
        #pragma unroll
        for (int dd = 0; dd < 8; dd++) {
            float4 fv = *(const float4*)(sh_p3 + (jt * 8 + dd) * 64 + rt * 4);
            accp[0 * 8 + dd] = fmaf(fv.x, wv0, accp[0 * 8 + dd]);
            accp[1 * 8 + dd] = fmaf(fv.y, wv1, accp[1 * 8 + dd]);
            accp[2 * 8 + dd] = fmaf(fv.z, wv2, accp[2 * 8 + dd]);
            accp[3 * 8 + dd] = fmaf(fv.w, wv3, accp[3 * 8 + dd]);
        }
    }
    __syncthreads();
    #pragma unroll
    for (int j = 0; j < 4; j++)
        #pragma unroll
        for (int dd = 0; dd < 8; dd++)
            sh_o[(rt * 4 + j) * 132 + jt * 8 + dd] = accp[j * 8 + dd];
    __syncthreads();
    for (int idx = tid; idx < 2048; idx += 256) {
        int r = idx >> 5, dq = (idx & 31) * 4;
        float4 a = *(const float4*)(sh_o + r * 132 + dq);
        *(float4*)(outp + (rowbase + r) * 128 + dq) = a;
    }
}

extern "C" void kernel_launch(void* const* d_in, const int* in_sizes, int n_in,
                              void* d_out, int out_size) {
    const float* x      = (const float*)d_in[0];
    const float* W1     = (const float*)d_in[1];
    const float* b1     = (const float*)d_in[2];
    const float* W2     = (const float*)d_in[3];
    const float* b2     = (const float*)d_in[4];
    const float* Wg     = (const float*)d_in[5];
    const float* bg     = (const float*)d_in[6];
    const float* Ws     = (const float*)d_in[7];
    const float* bs     = (const float*)d_in[8];
    const float* gamma  = (const float*)d_in[9];
    const float* beta   = (const float*)d_in[10];
    const float* sW1    = (const float*)d_in[11];
    const float* sb1    = (const float*)d_in[12];
    const float* sW2    = (const float*)d_in[13];
    const float* sb2    = (const float*)d_in[14];
    const float* sWg    = (const float*)d_in[15];
    const float* sbg    = (const float*)d_in[16];
    const float* sWs    = (const float*)d_in[17];
    const float* sbs    = (const float*)d_in[18];
    const float* sgamma = (const float*)d_in[19];
    const float* sbeta  = (const float*)d_in[20];

    int N = in_sizes[0] / 16;          // 16384
    int tiles64 = N / 64;              // 256
    int tiles128 = N / 128;            // 128

    float* outp = (float*)d_out;
    float* outw = outp + (size_t)N * 128;

    cudaFuncSetAttribute(vsn_stage1, cudaFuncAttributeMaxDynamicSharedMemorySize,
                         SM1_FLOATS * 4);
    cudaFuncSetAttribute(vsn_stage2, cudaFuncAttributeMaxDynamicSharedMemorySize, 84480);

    dim3 g1(tiles128, 16);
    vsn_stage1<<<g1, 256, SM1_FLOATS * 4>>>(x, W1, b1, W2, b2, Wg, bg, Ws, bs, gamma, beta);
    vsn_stage2<<<tiles64, 256, 84480>>>(sW1, sb1, sW2, sb2, sWg, sbg, sWs, sbs,
                                        sgamma, sbeta, outp, outw);
}

// round 11
// speedup vs baseline: 2.1792x; 1.2997x over previous
#include <cuda_runtime.h>
#include <cuda_bf16.h>
#include <cstdint>
#include <math.h>

#define NMAX 16384
__device__ __align__(256) float g_stackedT[(size_t)NMAX * 2048];

static __device__ __forceinline__ float eluf(float t) {
    return t > 0.f ? t : __expf(t) - 1.f;
}
static __device__ __forceinline__ float sigm(float t) {
    return __fdividef(1.f, 1.f + __expf(-t));
}

// pack two floats to bf16x2: lo -> low half (even k), hi -> high half (odd k)
static __device__ __forceinline__ uint32_t pk_bf2(float lo, float hi) {
    uint32_t r;
    asm("cvt.rn.bf16x2.f32 %0, %1, %2;" : "=r"(r) : "f"(hi), "f"(lo));
    return r;
}
// bf16 2-way split of a pair of values -> packed hi-pair and lo-pair
static __device__ __forceinline__ void bsplit2(float x0, float x1,
                                               uint32_t& hp, uint32_t& lp) {
    float h0 = __bfloat162float(__float2bfloat16(x0));
    float h1 = __bfloat162float(__float2bfloat16(x1));
    hp = pk_bf2(h0, h1);
    lp = pk_bf2(x0 - h0, x1 - h1);
}
static __device__ __forceinline__ void mma16(float* c, const uint32_t* a,
                                             uint32_t b0, uint32_t b1) {
    asm volatile(
        "mma.sync.aligned.m16n8k16.row.col.f32.bf16.bf16.f32 "
        "{%0,%1,%2,%3}, {%4,%5,%6,%7}, {%8,%9}, {%0,%1,%2,%3};"
        : "+f"(c[0]), "+f"(c[1]), "+f"(c[2]), "+f"(c[3])
        : "r"(a[0]), "r"(a[1]), "r"(a[2]), "r"(a[3]), "r"(b0), "r"(b1));
}

// ---------------------------------------------------------------------------
// Stage 1 (bf16 mma m16n8k16, 3-term split): grid (N/128, 16), 512 threads.
// A = h (128x128), B = [W2;Wg] (256x128), C (128x256) fp32 fragments.
// Warp w: mp=w&3 (rows 32mp..+31), nq=w>>2 (B-row quarter: 64 n's = 8 nt).
// K chunked by 32 (16 bf16-pairs), 2 k16 MMA steps per chunk.
// ---------------------------------------------------------------------------
#define SM1_FLOATS 36224
__global__ void __launch_bounds__(512, 1) vsn_stage1(
    const float* __restrict__ x,
    const float* __restrict__ W1, const float* __restrict__ b1,
    const float* __restrict__ W2, const float* __restrict__ b2,
    const float* __restrict__ Wg, const float* __restrict__ bg,
    const float* __restrict__ Ws, const float* __restrict__ bs,
    const float* __restrict__ gamma, const float* __restrict__ beta)
{
    extern __shared__ float sm[];
    // staging (u32 views) overlays arr1 region; used only during GEMM
    uint32_t* A_hi = (uint32_t*)sm;            // [128][20]
    uint32_t* A_lo = (uint32_t*)(sm + 2560);   // [128][20]
    uint32_t* B_hi = (uint32_t*)(sm + 5120);   // [256][20]
    uint32_t* B_lo = (uint32_t*)(sm + 10240);  // [256][20] -> end 15360
    float* arr1 = sm;               // [128][133] h2 / y (post-GEMM overlay)
    float* arr2 = sm + 17024;       // [128][133] gate
    float* par  = sm + 34048;       // b2,bg,Ws,bs,gamma,beta (128 each)
    float* sx   = sm + 34816;       // [128]
    float* pmean = sm + 34944;
    float* prstd = sm + 35072;
    float* part_s = sm + 35200;     // [4][128]
    float* part_q = sm + 35712;     // [4][128]

    const int tid = threadIdx.x, wid = tid >> 5, lane = tid & 31;
    const int mp = wid & 3, nq = wid >> 2;     // nq 0..3
    const int v = blockIdx.y;
    const int r0 = blockIdx.x * 128;
    const int ar = lane >> 2, ac = lane & 3;

    if (tid < 128) {
        sx[tid] = x[(size_t)(r0 + tid) * 16 + v];
        int o = tid;
        par[o]       = b2[v * 128 + o];
        par[128 + o] = bg[v * 128 + o];
        par[256 + o] = Ws[v * 128 + o];
        par[384 + o] = bs[v * 128 + o];
        par[512 + o] = gamma[v * 128 + o];
        par[640 + o] = beta[v * 128 + o];
    }

    float cfr[2][8][4];
    #pragma unroll
    for (int mi = 0; mi < 2; mi++)
        #pragma unroll
        for (int nt = 0; nt < 8; nt++)
            #pragma unroll
            for (int q = 0; q < 4; q++) cfr[mi][nt][q] = 0.f;

    for (int kc = 0; kc < 4; kc++) {     // K chunks of 32
        __syncthreads();
        const float* W1v = W1 + v * 128 + kc * 32;
        const float* b1v = b1 + v * 128 + kc * 32;
        // A = h chunk: 128 rows x 16 kpairs
        for (int idx = tid; idx < 2048; idx += 512) {
            int r = idx & 127, kp = idx >> 7;
            int d = kp * 2;
            float xr = sx[r];
            float h0 = eluf(fmaf(xr, W1v[d], b1v[d]));
            float h1 = eluf(fmaf(xr, W1v[d + 1], b1v[d + 1]));
            uint32_t hp, lp;
            bsplit2(h0, h1, hp, lp);
            A_hi[r * 20 + kp] = hp;
            A_lo[r * 20 + kp] = lp;
        }
        // B = [W2;Wg] chunk: 256 rows x 16 kpairs
        for (int idx = tid; idx < 4096; idx += 512) {
            int n = idx >> 4, kp = idx & 15;
            const float* src = (n < 128)
                ? W2 + ((size_t)v * 128 + n) * 128 + kc * 32 + kp * 2
                : Wg + ((size_t)v * 128 + (n - 128)) * 128 + kc * 32 + kp * 2;
            float2 a = *(const float2*)src;
            uint32_t hp, lp;
            bsplit2(a.x, a.y, hp, lp);
            B_hi[n * 20 + kp] = hp;
            B_lo[n * 20 + kp] = lp;
        }
        __syncthreads();

        #pragma unroll
        for (int ks = 0; ks < 2; ks++) {     // k16 steps
            const int k0p = ks * 8;
            uint32_t aH[2][4], aL[2][4];
            #pragma unroll
            for (int mi = 0; mi < 2; mi++) {
                int rb = (mp * 32 + mi * 16 + ar) * 20 + k0p + ac;
                aH[mi][0] = A_hi[rb];
                aH[mi][1] = A_hi[rb + 8 * 20];
                aH[mi][2] = A_hi[rb + 4];
                aH[mi][3] = A_hi[rb + 8 * 20 + 4];
                aL[mi][0] = A_lo[rb];
                aL[mi][1] = A_lo[rb + 8 * 20];
                aL[mi][2] = A_lo[rb + 4];
                aL[mi][3] = A_lo[rb + 8 * 20 + 4];
            }
            #pragma unroll
            for (int nt = 0; nt < 8; nt++) {
                int nb = (nq * 64 + nt * 8 + ar) * 20 + k0p + ac;
                uint32_t bH0 = B_hi[nb], bH1 = B_hi[nb + 4];
                uint32_t bL0 = B_lo[nb], bL1 = B_lo[nb + 4];
                mma16(cfr[0][nt], aH[0], bH0, bH1);
                mma16(cfr[1][nt], aH[1], bH0, bH1);
                mma16(cfr[0][nt], aL[0], bH0, bH1);
                mma16(cfr[1][nt], aL[1], bH0, bH1);
                mma16(cfr[0][nt], aH[0], bL0, bL1);
                mma16(cfr[1][nt], aH[1], bL0, bL1);
            }
        }
    }
    __syncthreads();

    // frags -> arr1 (h2+b2, nq 0/1) or arr2 (sigmoid gate, nq 2/3)
    {
        const int ac2 = ac * 2;
        #pragma unroll
        for (int mi = 0; mi < 2; mi++) {
            #pragma unroll
            for (int half = 0; half < 2; half++) {
                int r = mp * 32 + mi * 16 + ar + half * 8;
                #pragma unroll
                for (int nt = 0; nt < 8; nt++) {
                    int n = (nq & 1) * 64 + nt * 8 + ac2;
                    float v0 = cfr[mi][nt][half * 2];
                    float v1 = cfr[mi][nt][half * 2 + 1];
                    if (nq < 2) {
                        arr1[r * 133 + n]     = v0 + par[n];
                        arr1[r * 133 + n + 1] = v1 + par[n + 1];
                    } else {
                        arr2[r * 133 + n]     = sigm(v0 + par[128 + n]);
                        arr2[r * 133 + n + 1] = sigm(v1 + par[128 + n + 1]);
                    }
                }
            }
        }
    }
    __syncthreads();

    // gate/skip combine + LN partials: thread = (row, quarter of o's)
    {
        int r = tid & 127, hf = tid >> 7;       // hf 0..3
        float xr = sx[r];
        float s = 0.f, s2 = 0.f;
        int o0 = hf * 32;
        for (int o = o0; o < o0 + 32; o++) {
            float h2 = arr1[r * 133 + o];
            float g  = arr2[r * 133 + o];
            float sk = fmaf(xr, par[256 + o], par[384 + o]);
            float yv = g * h2 + (1.f - g) * sk;
            arr1[r * 133 + o] = yv;
            s += yv;
            s2 = fmaf(yv, yv, s2);
        }
        part_s[hf * 128 + r] = s;
        part_q[hf * 128 + r] = s2;
    }
    __syncthreads();
    if (tid < 128) {
        float s  = part_s[tid] + part_s[128 + tid] + part_s[256 + tid] + part_s[384 + tid];
        float s2 = part_q[tid] + part_q[128 + tid] + part_q[256 + tid] + part_q[384 + tid];
        float m = s * 0.0078125f;
        pmean[tid] = m;
        prstd[tid] = rsqrtf(fmaf(-m, m, s2 * 0.0078125f) + 1e-5f);
    }
    __syncthreads();

    // normalize + transposed write (64-row tile layout)
    {
        float* dst0 = g_stackedT + ((size_t)(blockIdx.x * 2) * 2048 + v * 128) * 64;
        for (int idx = tid; idx < 16384; idx += 512) {
            int o = idx >> 7, r = idx & 127;
            float val = fmaf((arr1[r * 133 + o] - pmean[r]) * prstd[r],
                             par[512 + o], par[640 + o]);
            dst0[(size_t)(r >> 6) * 2048 * 64 + o * 64 + (r & 63)] = val;
        }
    }
}

// ---------------------------------------------------------------------------
// Stage 2: R10 version verbatim (346 us measured). K-chunk 64, 2 CTAs/SM.
// ---------------------------------------------------------------------------
__global__ void __launch_bounds__(256, 2) vsn_stage2(
    const float* __restrict__ sW1, const float* __restrict__ sb1,
    const float* __restrict__ sW2, const float* __restrict__ sb2,
    const float* __restrict__ sWg, const float* __restrict__ sbg,
    const float* __restrict__ sWs, const float* __restrict__ sbs,
    const float* __restrict__ sgamma, const float* __restrict__ sbeta,
    float* __restrict__ outp, float* __restrict__ outw)
{
    extern __shared__ float sm[];
    float* sh_f  = sm;            // [64 k][64 r]
    float* warea = sm + 4096;     // multi-use
    float* sh_ws = sm + 16768;    // [16][68]
    float* sh_sk = sm + 17856;    // [64][17]
    float* sh_z  = sm + 18944;    // [64][17]
    float* sh_w  = sm + 20032;    // [64][17]  -> 21120 floats = 84480 B
    float* sh_w1 = warea;         // [128][68] during GEMM
    float* sh_hs = warea;         // [64][133] after
    float* sh_s2 = warea + 8512;  // [16][130]
    float* sh_sg = warea + 10592; // [16][130]
    float* sh_p3 = warea;         // [128][64] pass-3 tile
    float* sh_o  = warea;         // [64][132] output staging

    const int tid = threadIdx.x;
    const int rt = tid & 15, jt = tid >> 4;
    const int tile = blockIdx.x;
    const size_t rowbase = (size_t)tile * 64;
    const float* fbase = g_stackedT + (size_t)tile * 2048 * 64;

    float acc[32], accs[4];
    #pragma unroll
    for (int i = 0; i < 32; i++) acc[i] = 0.f;
    accs[0] = accs[1] = accs[2] = accs[3] = 0.f;

    for (int c = 0; c < 32; c++) {
        __syncthreads();
        {
            const float4* src = (const float4*)(fbase + (size_t)c * 64 * 64);
            float4* dst = (float4*)sh_f;
            for (int idx = tid; idx < 1024; idx += 256) dst[idx] = src[idx];
        }
        for (int idx = tid; idx < 2048; idx += 256) {
            int j = idx >> 4, kq = (idx & 15) * 4;
            float4 a = *(const float4*)(sW1 + (size_t)j * 2048 + c * 64 + kq);
            float* p = sh_w1 + j * 68 + kq;
            p[0] = a.x; p[1] = a.y; p[2] = a.z; p[3] = a.w;
        }
        {
            int idx = tid;
            if (idx < 256) {
                int vv = idx >> 4, kq = (idx & 15) * 4;
                float4 a = *(const float4*)(sWs + (size_t)vv * 2048 + c * 64 + kq);
                float* p = sh_ws + vv * 68 + kq;
                p[0] = a.x; p[1] = a.y; p[2] = a.z; p[3] = a.w;
            }
        }
        __syncthreads();
        #pragma unroll 8
        for (int kk = 0; kk < 64; kk++) {
            float4 fv = *(const float4*)(sh_f + kk * 64 + rt * 4);
            float wsv = sh_ws[jt * 68 + kk];
            accs[0] = fmaf(fv.x, wsv, accs[0]);
            accs[1] = fmaf(fv.y, wsv, accs[1]);
            accs[2] = fmaf(fv.z, wsv, accs[2]);
            accs[3] = fmaf(fv.w, wsv, accs[3]);
            #pragma unroll
            for (int i = 0; i < 8; i++) {
                float w = sh_w1[(jt * 8 + i) * 68 + kk];
                acc[0 * 8 + i] = fmaf(fv.x, w, acc[0 * 8 + i]);
                acc[1 * 8 + i] = fmaf(fv.y, w, acc[1 * 8 + i]);
                acc[2 * 8 + i] = fmaf(fv.z, w, acc[2 * 8 + i]);
                acc[3 * 8 + i] = fmaf(fv.w, w, acc[3 * 8 + i]);
            }
        }
    }
    __syncthreads();

    #pragma unroll
    for (int j = 0; j < 4; j++)
        sh_sk[(rt * 4 + j) * 17 + jt] = accs[j] + sbs[jt];
    #pragma unroll
    for (int i = 0; i < 8; i++) {
        int jj = jt * 8 + i;
        float bb = sb1[jj];
        #pragma unroll
        for (int j = 0; j < 4; j++)
            sh_hs[(rt * 4 + j) * 133 + jj] = eluf(acc[j * 8 + i] + bb);
    }
    for (int idx = tid; idx < 512; idx += 256) {
        int vv = idx >> 5, jq = (idx & 31) * 4;
        float4 a = *(const float4*)(sW2 + vv * 128 + jq);
        float* p = sh_s2 + vv * 130 + jq;
        p[0] = a.x; p[1] = a.y; p[2] = a.z; p[3] = a.w;
        float4 b = *(const float4*)(sWg + vv * 128 + jq);
        float* q = sh_sg + vv * 130 + jq;
        q[0] = b.x; q[1] = b.y; q[2] = b.z; q[3] = b.w;
    }
    __syncthreads();
    {
        int q = tid & 3, r = tid >> 2;
        float a2[4] = {0.f, 0.f, 0.f, 0.f};
        float ag[4] = {0.f, 0.f, 0.f, 0.f};
        #pragma unroll 4
        for (int j = 0; j < 128; j++) {
            float hsv = sh_hs[r * 133 + j];
            #pragma unroll
            for (int i = 0; i < 4; i++) {
                a2[i] = fmaf(hsv, sh_s2[(q * 4 + i) * 130 + j], a2[i]);
                ag[i] = fmaf(hsv, sh_sg[(q * 4 + i) * 130 + j], ag[i]);
            }
        }
        #pragma unroll
        for (int i = 0; i < 4; i++) {
            int vv = q * 4 + i;
            float h2s = a2[i] + sb2[vv];
            float gs = sigm(ag[i] + sbg[vv]);
            float sk = sh_sk[r * 17 + vv];
            sh_z[r * 17 + vv] = gs * h2s + (1.f - gs) * sk;
        }
    }
    __syncthreads();
    if (tid < 64) {
        float zz[16];
        float s = 0.f;
        #pragma unroll
        for (int vv = 0; vv < 16; vv++) { zz[vv] = sh_z[tid * 17 + vv]; s += zz[vv]; }
        float m = s * 0.0625f;
        float s2 = 0.f;
        #pragma unroll
        for (int vv = 0; vv < 16; vv++) { float d = zz[vv] - m; s2 = fmaf(d, d, s2); }
        float rstd = rsqrtf(s2 * 0.0625f + 1e-5f);
        float mx = -3.4e38f;
        #pragma unroll
        for (int vv = 0; vv < 16; vv++) {
            zz[vv] = fmaf((zz[vv] - m) * rstd, sgamma[vv], sbeta[vv]);
            mx = fmaxf(mx, zz[vv]);
        }
        float se = 0.f;
        #pragma unroll
        for (int vv = 0; vv < 16; vv++) { zz[vv] = __expf(zz[vv] - mx); se += zz[vv]; }
        float inv = __fdividef(1.f, se);
        #pragma unroll
        for (int vv = 0; vv < 16; vv++) sh_w[tid * 17 + vv] = zz[vv] * inv;
    }
    __syncthreads();
    for (int idx = tid; idx < 1024; idx += 256) {
        int r = idx >> 4, vv = idx & 15;
        outw[(rowbase + r) * 16 + vv] = sh_w[r * 17 + vv];
    }

    float accp[32];
    #pragma unroll
    for (int i = 0; i < 32; i++) accp[i] = 0.f;
    for (int vv = 0; vv < 16; vv++) {
        __syncthreads();
        {
            const float4* src = (const float4*)(fbase + (size_t)vv * 128 * 64);
            float4* dst = (float4*)sh_p3;
            for (int idx = tid; idx < 2048; idx += 256) dst[idx] = src[idx];
        }
        __syncthreads();
        float wv0 = sh_w[(rt * 4 + 0) * 17 + vv];
        float wv1 = sh_w[(rt * 4 + 1) * 17 + vv];
        float wv2 = sh_w[(rt * 4 + 2) * 17 + vv];
        float wv3 = sh_w[(rt * 4 + 3) * 17 + vv];
        #pragma unroll
        for (int dd = 0; dd < 8; dd++) {
            float4 fv = *(const float4*)(sh_p3 + (jt * 8 + dd) * 64 + rt * 4);
            accp[0 * 8 + dd] = fmaf(fv.x, wv0, accp[0 * 8 + dd]);
            accp[1 * 8 + dd] = fmaf(fv.y, wv1, accp[1 * 8 + dd]);
            accp[2 * 8 + dd] = fmaf(fv.z, wv2, accp[2 * 8 + dd]);
            accp[3 * 8 + dd] = fmaf(fv.w, wv3, accp[3 * 8 + dd]);
        }
    }
    __syncthreads();
    #pragma unroll
    for (int j = 0; j < 4; j++)
        #pragma unroll
        for (int dd = 0; dd < 8; dd++)
            sh_o[(rt * 4 + j) * 132 + jt * 8 + dd] = accp[j * 8 + dd];
    __syncthreads();
    for (int idx = tid; idx < 2048; idx += 256) {
        int r = idx >> 5, dq = (idx & 31) * 4;
        float4 a = *(const float4*)(sh_o + r * 132 + dq);
        *(float4*)(outp + (rowbase + r) * 128 + dq) = a;
    }
}

extern "C" void kernel_launch(void* const* d_in, const int* in_sizes, int n_in,
                              void* d_out, int out_size) {
    const float* x      = (const float*)d_in[0];
    const float* W1     = (const float*)d_in[1];
    const float* b1     = (const float*)d_in[2];
    const float* W2     = (const float*)d_in[3];
    const float* b2     = (const float*)d_in[4];
    const float* Wg     = (const float*)d_in[5];
    const float* bg     = (const float*)d_in[6];
    const float* Ws     = (const float*)d_in[7];
    const float* bs     = (const float*)d_in[8];
    const float* gamma  = (const float*)d_in[9];
    const float* beta   = (const float*)d_in[10];
    const float* sW1    = (const float*)d_in[11];
    const float* sb1    = (const float*)d_in[12];
    const float* sW2    = (const float*)d_in[13];
    const float* sb2    = (const float*)d_in[14];
    const float* sWg    = (const float*)d_in[15];
    const float* sbg    = (const float*)d_in[16];
    const float* sWs    = (const float*)d_in[17];
    const float* sbs    = (const float*)d_in[18];
    const float* sgamma = (const float*)d_in[19];
    const float* sbeta  = (const float*)d_in[20];

    int N = in_sizes[0] / 16;          // 16384
    int tiles64 = N / 64;              // 256
    int tiles128 = N / 128;            // 128

    float* outp = (float*)d_out;
    float* outw = outp + (size_t)N * 128;

    cudaFuncSetAttribute(vsn_stage1, cudaFuncAttributeMaxDynamicSharedMemorySize,
                         SM1_FLOATS * 4);
    cudaFuncSetAttribute(vsn_stage2, cudaFuncAttributeMaxDynamicSharedMemorySize, 84480);

    dim3 g1(tiles128, 16);
    vsn_stage1<<<g1, 512, SM1_FLOATS * 4>>>(x, W1, b1, W2, b2, Wg, bg, Ws, bs, gamma, beta);
    vsn_stage2<<<tiles64, 256, 84480>>>(sW1, sb1, sW2, sb2, sWg, sbg, sWs, sbs,
                                        sgamma, sbeta, outp, outw);
}